// round 7
// baseline (speedup 1.0000x reference)
#include <cuda_runtime.h>
#include <cuda_bf16.h>
#include <math.h>
#include <stdint.h>

// Problem constants
#define Bn 4
#define Sn 2048
#define DIMn 1024
#define Hn 16
#define Dn 64
#define Tn (Bn*Sn)      // 8192 tokens
#define HDn 1024
#define WIN 512

typedef unsigned short ush;

// ---------------------------------------------------------------------------
// Scratch (device globals)
// ---------------------------------------------------------------------------
__device__ float g_mix[Tn*Hn];
__device__ float g_gate[Tn*Hn];

__device__ ush g_tokh[(size_t)Tn*DIMn];
__device__ ush g_tokl[(size_t)Tn*DIMn];
__device__ ush g_aoh[(size_t)Tn*HDn];
__device__ ush g_aol[(size_t)Tn*HDn];
__device__ ush g_wallh[3072*1024];   // [Wq | Wk | Wv] transposed, [N=3072, K=1024]
__device__ ush g_walll[3072*1024];
__device__ ush g_woh[1024*1024];
__device__ ush g_wol[1024*1024];
__device__ ush g_qsh[(size_t)Tn*HDn];
__device__ ush g_qsl[(size_t)Tn*HDn];
__device__ ush g_ksh[(size_t)Tn*HDn];
__device__ ush g_ksl[(size_t)Tn*HDn];
__device__ ush g_vsh[(size_t)Tn*HDn];
__device__ ush g_vsl[(size_t)Tn*HDn];

// ---------------------------------------------------------------------------
// Helpers (base sm_103 target — mma.sync / ldmatrix / cp.async, NO tcgen05)
// ---------------------------------------------------------------------------
__device__ __forceinline__ uint32_t smem_u32(const void* p) {
    uint32_t a;
    asm("{ .reg .u64 t; cvta.to.shared.u64 t, %1; cvt.u32.u64 %0, t; }" : "=r"(a) : "l"(p));
    return a;
}
__device__ __forceinline__ void ldsm4(uint32_t* r, uint32_t addr) {
    asm volatile("ldmatrix.sync.aligned.m8n8.x4.shared.b16 {%0,%1,%2,%3}, [%4];"
                 : "=r"(r[0]), "=r"(r[1]), "=r"(r[2]), "=r"(r[3]) : "r"(addr));
}
__device__ __forceinline__ void ldsm4t(uint32_t* r, uint32_t addr) {
    asm volatile("ldmatrix.sync.aligned.m8n8.x4.trans.shared.b16 {%0,%1,%2,%3}, [%4];"
                 : "=r"(r[0]), "=r"(r[1]), "=r"(r[2]), "=r"(r[3]) : "r"(addr));
}
__device__ __forceinline__ void mma16816(float* d, const uint32_t* a, const uint32_t* b) {
    asm volatile("mma.sync.aligned.m16n8k16.row.col.f32.bf16.bf16.f32 "
                 "{%0,%1,%2,%3},{%4,%5,%6,%7},{%8,%9},{%0,%1,%2,%3};"
                 : "+f"(d[0]), "+f"(d[1]), "+f"(d[2]), "+f"(d[3])
                 : "r"(a[0]), "r"(a[1]), "r"(a[2]), "r"(a[3]),
                   "r"(b[0]), "r"(b[1]));
}
__device__ __forceinline__ void cp16(uint32_t smem, const void* g) {
    asm volatile("cp.async.cg.shared.global [%0], [%1], 16;" :: "r"(smem), "l"(g));
}
__device__ __forceinline__ uint32_t packbf(float lo, float hi) {
    uint32_t r;
    asm("cvt.rn.bf16x2.f32 %0, %1, %2;" : "=r"(r) : "f"(hi), "f"(lo));
    return r;
}
__device__ __forceinline__ void split2(float x, ush& h, ush& l) {
    __nv_bfloat16 hb = __float2bfloat16_rn(x);
    float r = x - __bfloat162float(hb);
    __nv_bfloat16 lb = __float2bfloat16_rn(r);
    h = *reinterpret_cast<ush*>(&hb);
    l = *reinterpret_cast<ush*>(&lb);
}
__device__ __forceinline__ void splitpair(float y0, float y1, uint32_t& hp, uint32_t& lp) {
    hp = packbf(y0, y1);
    lp = packbf(y0 - __uint_as_float(hp << 16),
                y1 - __uint_as_float(hp & 0xFFFF0000u));
}

// ---------------------------------------------------------------------------
// fp32 -> bf16 hi/lo split (elementwise)
// ---------------------------------------------------------------------------
__global__ void convA(const float* __restrict__ x, ush* __restrict__ h,
                      ush* __restrict__ l, int n4)
{
    int i = blockIdx.x * blockDim.x + threadIdx.x;
    if (i >= n4) return;
    float4 v = ((const float4*)x)[i];
    float vs[4] = {v.x, v.y, v.z, v.w};
    ush hs[4], ls[4];
#pragma unroll
    for (int j = 0; j < 4; j++) split2(vs[j], hs[j], ls[j]);
    ((ushort4*)h)[i] = make_ushort4(hs[0], hs[1], hs[2], hs[3]);
    ((ushort4*)l)[i] = make_ushort4(ls[0], ls[1], ls[2], ls[3]);
}

// W [K,N] fp32 -> Wt_hi/lo [N,K] bf16 (transpose via smem)
__global__ void convW(const float* __restrict__ W, ush* __restrict__ Th,
                      ush* __restrict__ Tl, int K, int N)
{
    __shared__ float t[32][33];
    int n0 = blockIdx.x * 32, k0 = blockIdx.y * 32;
    int tx = threadIdx.x, ty = threadIdx.y;   // blockDim (32, 8)
#pragma unroll
    for (int r = 0; r < 4; r++)
        t[ty + 8 * r][tx] = W[(size_t)(k0 + ty + 8 * r) * N + n0 + tx];
    __syncthreads();
#pragma unroll
    for (int r = 0; r < 4; r++) {
        float v = t[tx][ty + 8 * r];
        size_t o = (size_t)(n0 + ty + 8 * r) * K + k0 + tx;
        ush hh, ll;
        split2(v, hh, ll);
        Th[o] = hh; Tl[o] = ll;
    }
}

// ---------------------------------------------------------------------------
// HMMA bf16x3 GEMM: 256 threads, 8 warps (4m x 2n), warp tile 32x64,
// CTA 128x128, K-chunk 32, 4-stage cp.async + register fragment pipeline.
// mode 0: fp32 C store. mode 1: fused QKV epilogue (rope / v-mix -> splits).
// ---------------------------------------------------------------------------
#define PADE 40
#define KIND_ELEMS (128*PADE)            // 5120 ush = 10KB
#define STAGE_ELEMS (4*KIND_ELEMS)       // 40KB
#define NSTAGE 4
#define GEMM_SMEM (NSTAGE*STAGE_ELEMS*2) // 163840 B

// fragment load: (stage slot, ksub) -> named register arrays (compile-time)
#define LDFRAGS(slot, ksub, AF, BF) do {                                    \
    uint32_t base_ = sbase + (uint32_t)(slot) * (STAGE_ELEMS * 2);          \
    int arow_ = wm + (lane & 15);                                           \
    int acol_ = (ksub) * 16 + (lane >> 4) * 8;                              \
    _Pragma("unroll")                                                       \
    for (int sp_ = 0; sp_ < 2; sp_++) {                                     \
        _Pragma("unroll")                                                   \
        for (int ms_ = 0; ms_ < 2; ms_++)                                   \
            ldsm4(AF[sp_][ms_], base_ + (uint32_t)(sp_ * KIND_ELEMS +       \
                  (arow_ + ms_ * 16) * PADE + acol_) * 2);                  \
    }                                                                       \
    int bn_ = (lane & 7) | ((lane >> 1) & 8);                               \
    int bk_ = (ksub) * 16 + ((lane >> 3) & 1) * 8;                          \
    _Pragma("unroll")                                                       \
    for (int sp_ = 0; sp_ < 2; sp_++) {                                     \
        _Pragma("unroll")                                                   \
        for (int g_ = 0; g_ < 4; g_++) {                                    \
            uint32_t r_[4];                                                 \
            ldsm4(r_, base_ + (uint32_t)((2 + sp_) * KIND_ELEMS +           \
                  (wn + g_ * 16 + bn_) * PADE + bk_) * 2);                  \
            BF[sp_][2*g_][0]   = r_[0]; BF[sp_][2*g_][1]   = r_[1];         \
            BF[sp_][2*g_+1][0] = r_[2]; BF[sp_][2*g_+1][1] = r_[3];         \
        }                                                                   \
    }                                                                       \
} while (0)

#define MMA_ALL(AF, BF) do {                                                \
    _Pragma("unroll")                                                       \
    for (int ms_ = 0; ms_ < 2; ms_++) {                                     \
        _Pragma("unroll")                                                   \
        for (int nf_ = 0; nf_ < 8; nf_++) {                                 \
            mma16816(acc[ms_][nf_], AF[0][ms_], BF[0][nf_]);                \
            mma16816(acc[ms_][nf_], AF[0][ms_], BF[1][nf_]);                \
            mma16816(acc[ms_][nf_], AF[1][ms_], BF[0][nf_]);                \
        }                                                                   \
    }                                                                       \
} while (0)

__global__ void __launch_bounds__(256) gemm_mma(
    const ush* __restrict__ Ah, const ush* __restrict__ Al,
    const ush* __restrict__ Bh, const ush* __restrict__ Bl,
    float* __restrict__ C,
    ush* __restrict__ qh, ush* __restrict__ ql,
    ush* __restrict__ kh, ush* __restrict__ kl,
    ush* __restrict__ vh, ush* __restrict__ vl,
    const float* __restrict__ vres, const float* __restrict__ mix,
    int mode)
{
    extern __shared__ ush sh[];
    const int tid  = threadIdx.x;
    const int wid  = tid >> 5, lane = tid & 31;
    const int brow = blockIdx.y * 128, bcol = blockIdx.x * 128;
    const int wm   = (wid & 3) * 32;
    const int wn   = (wid >> 2) * 64;
    const int K    = 1024;

    const uint32_t sbase = smem_u32(sh);

    float acc[2][8][4];
#pragma unroll
    for (int i = 0; i < 2; i++)
#pragma unroll
        for (int j = 0; j < 8; j++)
#pragma unroll
            for (int k = 0; k < 4; k++) acc[i][j][k] = 0.f;

    const ush* srcs[4] = {Ah, Al, Bh, Bl};
    const int rbase[4] = {brow, brow, bcol, bcol};

    auto cp_stage = [&](int cidx) {
        int k0 = cidx * 32;
        int st = cidx & (NSTAGE - 1);
#pragma unroll
        for (int kind = 0; kind < 4; kind++) {
#pragma unroll
            for (int half = 0; half < 2; half++) {
                int e = tid + half * 256;
                int row = e >> 2, ce = (e & 3) * 8;
                const ush* g = srcs[kind] + (size_t)(rbase[kind] + row) * K + k0 + ce;
                uint32_t d = sbase + (uint32_t)(st * STAGE_ELEMS + kind * KIND_ELEMS +
                                                row * PADE + ce) * 2;
                cp16(d, g);
            }
        }
        asm volatile("cp.async.commit_group;" ::: "memory");
    };

    // register fragment double buffers (compile-time indexed)
    uint32_t aF0[2][2][4], bF0[2][8][2];
    uint32_t aF1[2][2][4], bF1[2][8][2];

    cp_stage(0); cp_stage(1); cp_stage(2);
    asm volatile("cp.async.wait_group 2;" ::: "memory");
    __syncthreads();
    LDFRAGS(0, 0, aF0, bF0);

    for (int c = 0; c < 32; c++) {
        // stages c and c+1 complete after this wait (uniform group counting)
        asm volatile("cp.async.wait_group 1;" ::: "memory");
        __syncthreads();
        if (c + 3 < 32) cp_stage(c + 3);
        else asm volatile("cp.async.commit_group;" ::: "memory");

        // ksub 0: prefetch ksub1 frags, compute ksub0
        LDFRAGS(c & (NSTAGE - 1), 1, aF1, bF1);
        MMA_ALL(aF0, bF0);
        // ksub 1: prefetch next chunk's ksub0 frags (stage c+1 resident), compute ksub1
        if (c + 1 < 32) { LDFRAGS((c + 1) & (NSTAGE - 1), 0, aF0, bF0); }
        MMA_ALL(aF1, bF1);
    }

    if (mode == 0) {
#pragma unroll
        for (int ms = 0; ms < 2; ms++) {
            int r0 = brow + wm + ms * 16 + (lane >> 2);
#pragma unroll
            for (int nf = 0; nf < 8; nf++) {
                int cc = bcol + wn + nf * 8 + 2 * (lane & 3);
                *(float2*)(C + (size_t)r0 * 1024 + cc)       = make_float2(acc[ms][nf][0], acc[ms][nf][1]);
                *(float2*)(C + (size_t)(r0 + 8) * 1024 + cc) = make_float2(acc[ms][nf][2], acc[ms][nf][3]);
            }
        }
        return;
    }

    // fused QKV epilogue: seg 0=q (rope+scale), 1=k (rope), 2=v (mix lerp)
    const int seg  = bcol >> 10;
    const int colb = (bcol & 1023) + wn + 2 * (lane & 3);
    ush* dh = (seg == 0) ? qh : (seg == 1) ? kh : vh;
    ush* dl = (seg == 0) ? ql : (seg == 1) ? kl : vl;
    const float qscale = (seg == 0) ? 0.125f : 1.0f;
    const float L2F = 13.2877123795494f / 32.0f;   // log2(10000)/32

#pragma unroll
    for (int ms = 0; ms < 2; ms++) {
        int r0 = brow + wm + ms * 16 + (lane >> 2);
#pragma unroll
        for (int half = 0; half < 2; half++) {
            int row = r0 + half * 8;
            int s = row & (Sn - 1);
            int bb = row >> 11;
#pragma unroll
            for (int nf = 0; nf < 8; nf++) {
                float x0 = acc[ms][nf][half * 2 + 0];
                float x1 = acc[ms][nf][half * 2 + 1];
                int colc = colb + nf * 8;
                float y0, y1;
                if (seg < 2) {
                    int i = (colc & 63) >> 1;
                    float inv = exp2f(-(float)i * L2F);
                    float ang = (float)s * inv;
                    float sn, cs;
                    sincosf(ang, &sn, &cs);
                    y0 = (x0 * cs - x1 * sn) * qscale;
                    y1 = (x1 * cs + x0 * sn) * qscale;
                } else {
                    int hh = (colc & 1023) >> 6;
                    int d  = colc & 63;
                    float m = mix[row * Hn + hh];
                    const float* rp = vres + (((size_t)bb * Hn + hh) * Sn + s) * Dn + d;
                    float2 rr = *(const float2*)rp;
                    y0 = x0 + (rr.x - x0) * m;
                    y1 = x1 + (rr.y - x1) * m;
                }
                uint32_t hp, lp;
                splitpair(y0, y1, hp, lp);
                size_t o = (size_t)row * 1024 + colc;
                *(uint32_t*)(dh + o) = hp;
                *(uint32_t*)(dl + o) = lp;
            }
        }
    }
}

// ---------------------------------------------------------------------------
// mix/gate: (8192 x 1024) @ [Wmix | Wgate] (1024 x 32), sigmoid epilogue.
// ---------------------------------------------------------------------------
__global__ void __launch_bounds__(256) mixgate(
    const float* __restrict__ tokens, const float* __restrict__ Wmix,
    const float* __restrict__ Wgate, float* __restrict__ gmix,
    float* __restrict__ ggate)
{
    __shared__ float Ts[128][65];
    __shared__ float Ws[64][32];

    const int tid  = threadIdx.x;
    const int row0 = blockIdx.x * 128;
    const int r  = tid >> 1;
    const int cg = (tid & 1) << 4;

    float acc[16];
#pragma unroll
    for (int c = 0; c < 16; c++) acc[c] = 0.f;

    for (int k0 = 0; k0 < 1024; k0 += 64) {
#pragma unroll
        for (int u = 0; u < 8; u++) {
            int fi = tid + u * 256;
            int rr = fi >> 4;
            int cc = (fi & 15) << 2;
            float4 x = *(const float4*)(tokens + (size_t)(row0 + rr) * 1024 + k0 + cc);
            Ts[rr][cc] = x.x; Ts[rr][cc + 1] = x.y; Ts[rr][cc + 2] = x.z; Ts[rr][cc + 3] = x.w;
        }
#pragma unroll
        for (int u = 0; u < 8; u++) {
            int fi = tid + u * 256;
            int rr = fi >> 5;
            int cc = fi & 31;
            Ws[rr][cc] = (cc < 16) ? Wmix[(k0 + rr) * 16 + cc]
                                   : Wgate[(k0 + rr) * 16 + (cc - 16)];
        }
        __syncthreads();
        for (int kk = 0; kk < 64; kk++) {
            float a = Ts[r][kk];
#pragma unroll
            for (int c = 0; c < 16; c++) acc[c] += a * Ws[kk][cg + c];
        }
        __syncthreads();
    }

    const int t = row0 + r;
#pragma unroll
    for (int c = 0; c < 16; c++) {
        float sg = 1.0f / (1.0f + expf(-acc[c]));
        int col = cg + c;
        if (col < 16) gmix[t * 16 + col] = sg;
        else          ggate[t * 16 + (col - 16)] = sg;
    }
}

// ---------------------------------------------------------------------------
// Sliding-window flash attention, HMMA bf16x3, online softmax in registers.
// ---------------------------------------------------------------------------
#define APAD 72
#define ATT_SMEM (6*64*APAD*2)

__global__ void __launch_bounds__(128) attn_mma(
    const ush* __restrict__ qh, const ush* __restrict__ ql,
    const ush* __restrict__ kh, const ush* __restrict__ kl,
    const ush* __restrict__ vh, const ush* __restrict__ vl,
    const float* __restrict__ gate,
    ush* __restrict__ aoh, ush* __restrict__ aol)
{
    extern __shared__ ush smA[];
    ush* Qh = smA;
    ush* Ql = Qh + 64 * APAD;
    ush* Kh = Ql + 64 * APAD;
    ush* Kl = Kh + 64 * APAD;
    ush* Vh = Kl + 64 * APAD;
    ush* Vl = Vh + 64 * APAD;

    const int b = blockIdx.z, h = blockIdx.y, q0 = blockIdx.x * 64;
    const int tid = threadIdx.x, wid = tid >> 5, lane = tid & 31;
    const int wm = wid * 16;
    const size_t bbase = (size_t)b * Sn;
    const int hoff = h * Dn;

#pragma unroll
    for (int i = 0; i < 4; i++) {
        int e = tid + i * 128;
        int row = e >> 3, c = (e & 7) * 8;
        size_t g = (bbase + q0 + row) * (size_t)HDn + hoff + c;
        *(uint4*)(Qh + row * APAD + c) = *(const uint4*)(qh + g);
        *(uint4*)(Ql + row * APAD + c) = *(const uint4*)(ql + g);
    }
    __syncthreads();

    uint32_t qfh[4][4], qfl[4][4];
    {
        uint32_t qb = smem_u32(Qh), qbl = smem_u32(Ql);
        int arow = wm + (lane & 15);
        int ac0  = (lane >> 4) * 8;
#pragma unroll
        for (int ks = 0; ks < 4; ks++) {
            ldsm4(qfh[ks], qb  + (arow * APAD + ks * 16 + ac0) * 2);
            ldsm4(qfl[ks], qbl + (arow * APAD + ks * 16 + ac0) * 2);
        }
    }

    float mi0 = -1e30f, mi1 = -1e30f, li0 = 0.f, li1 = 0.f;
    float accO[8][4];
#pragma unroll
    for (int i = 0; i < 8; i++)
#pragma unroll
        for (int j = 0; j < 4; j++) accO[i][j] = 0.f;

    const int jt_lo = (q0 >= WIN) ? ((q0 - WIN) >> 6) : 0;
    const int jt_hi = q0 >> 6;
    const int gi0 = q0 + wm + (lane >> 2);
    const int gi1 = gi0 + 8;

    const uint32_t kb  = smem_u32(Kh), kbl = smem_u32(Kl);
    const uint32_t vb  = smem_u32(Vh), vbl = smem_u32(Vl);
    const int bn  = (lane & 7) | ((lane >> 1) & 8);
    const int bk8 = ((lane >> 3) & 1) * 8;
    const int vr0 = lane & 15;
    const int vc8 = (lane >> 4) * 8;

    for (int jt = jt_lo; jt <= jt_hi; jt++) {
        const int j0 = jt * 64;
#pragma unroll
        for (int i = 0; i < 4; i++) {
            int e = tid + i * 128;
            int row = e >> 3, c = (e & 7) * 8;
            size_t g = (bbase + j0 + row) * (size_t)HDn + hoff + c;
            *(uint4*)(Kh + row * APAD + c) = *(const uint4*)(kh + g);
            *(uint4*)(Kl + row * APAD + c) = *(const uint4*)(kl + g);
            *(uint4*)(Vh + row * APAD + c) = *(const uint4*)(vh + g);
            *(uint4*)(Vl + row * APAD + c) = *(const uint4*)(vl + g);
        }
        __syncthreads();

        float s[8][4];
#pragma unroll
        for (int i = 0; i < 8; i++)
#pragma unroll
            for (int j = 0; j < 4; j++) s[i][j] = 0.f;

#pragma unroll
        for (int ks = 0; ks < 4; ks++) {
#pragma unroll
            for (int g2 = 0; g2 < 4; g2++) {
                uint32_t off = (uint32_t)(((g2 * 16 + bn) * APAD + ks * 16 + bk8) * 2);
                uint32_t rh[4], rl[4];
                ldsm4(rh, kb  + off);
                ldsm4(rl, kbl + off);
                uint32_t bh0[2] = {rh[0], rh[1]}, bh1[2] = {rh[2], rh[3]};
                uint32_t bl0[2] = {rl[0], rl[1]}, bl1[2] = {rl[2], rl[3]};
                mma16816(s[2*g2],   qfh[ks], bh0);
                mma16816(s[2*g2],   qfh[ks], bl0);
                mma16816(s[2*g2],   qfl[ks], bh0);
                mma16816(s[2*g2+1], qfh[ks], bh1);
                mma16816(s[2*g2+1], qfh[ks], bl1);
                mma16816(s[2*g2+1], qfl[ks], bh1);
            }
        }

        if (jt == jt_hi || (jt == jt_lo && q0 >= WIN)) {
#pragma unroll
            for (int nf = 0; nf < 8; nf++) {
                int cbase = j0 + nf * 8 + (lane & 3) * 2;
#pragma unroll
                for (int jj = 0; jj < 2; jj++) {
                    int gj = cbase + jj;
                    int d0 = gi0 - gj, d1 = gi1 - gj;
                    if (d0 < 0 || d0 > WIN) s[nf][jj]     = -1e30f;
                    if (d1 < 0 || d1 > WIN) s[nf][2 + jj] = -1e30f;
                }
            }
        }

        float mt0 = -1e30f, mt1 = -1e30f;
#pragma unroll
        for (int nf = 0; nf < 8; nf++) {
            mt0 = fmaxf(mt0, fmaxf(s[nf][0], s[nf][1]));
            mt1 = fmaxf(mt1, fmaxf(s[nf][2], s[nf][3]));
        }
        mt0 = fmaxf(mt0, __shfl_xor_sync(0xffffffffu, mt0, 1));
        mt0 = fmaxf(mt0, __shfl_xor_sync(0xffffffffu, mt0, 2));
        mt1 = fmaxf(mt1, __shfl_xor_sync(0xffffffffu, mt1, 1));
        mt1 = fmaxf(mt1, __shfl_xor_sync(0xffffffffu, mt1, 2));

        float mn0 = fmaxf(mi0, mt0), mn1 = fmaxf(mi1, mt1);
        float f0 = __expf(mi0 - mn0), f1 = __expf(mi1 - mn1);
        mi0 = mn0; mi1 = mn1;

        float su0 = 0.f, su1 = 0.f;
#pragma unroll
        for (int nf = 0; nf < 8; nf++) {
            s[nf][0] = __expf(s[nf][0] - mn0);
            s[nf][1] = __expf(s[nf][1] - mn0);
            s[nf][2] = __expf(s[nf][2] - mn1);
            s[nf][3] = __expf(s[nf][3] - mn1);
            su0 += s[nf][0] + s[nf][1];
            su1 += s[nf][2] + s[nf][3];
        }
        su0 += __shfl_xor_sync(0xffffffffu, su0, 1);
        su0 += __shfl_xor_sync(0xffffffffu, su0, 2);
        su1 += __shfl_xor_sync(0xffffffffu, su1, 1);
        su1 += __shfl_xor_sync(0xffffffffu, su1, 2);
        li0 = li0 * f0 + su0;
        li1 = li1 * f1 + su1;
#pragma unroll
        for (int nf = 0; nf < 8; nf++) {
            accO[nf][0] *= f0; accO[nf][1] *= f0;
            accO[nf][2] *= f1; accO[nf][3] *= f1;
        }

#pragma unroll
        for (int ks = 0; ks < 4; ks++) {
            uint32_t ph[4], pl[4];
            const float* p0 = s[2 * ks];
            const float* p1 = s[2 * ks + 1];
            splitpair(p0[0], p0[1], ph[0], pl[0]);
            splitpair(p0[2], p0[3], ph[1], pl[1]);
            splitpair(p1[0], p1[1], ph[2], pl[2]);
            splitpair(p1[2], p1[3], ph[3], pl[3]);
#pragma unroll
            for (int g2 = 0; g2 < 4; g2++) {
                uint32_t off = (uint32_t)(((ks * 16 + vr0) * APAD + g2 * 16 + vc8) * 2);
                uint32_t rh[4], rl[4];
                ldsm4t(rh, vb  + off);
                ldsm4t(rl, vbl + off);
                uint32_t bh0[2] = {rh[0], rh[1]}, bh1[2] = {rh[2], rh[3]};
                uint32_t bl0[2] = {rl[0], rl[1]}, bl1[2] = {rl[2], rl[3]};
                mma16816(accO[2*g2],   ph, bh0);
                mma16816(accO[2*g2],   ph, bl0);
                mma16816(accO[2*g2],   pl, bh0);
                mma16816(accO[2*g2+1], ph, bh1);
                mma16816(accO[2*g2+1], ph, bl1);
                mma16816(accO[2*g2+1], pl, bh1);
            }
        }
        __syncthreads();
    }

    float g0 = gate[(bbase + gi0) * Hn + h];
    float g1 = gate[(bbase + gi1) * Hn + h];
    float sc0 = g0 / li0, sc1 = g1 / li1;
#pragma unroll
    for (int nf = 0; nf < 8; nf++) {
        int col = hoff + nf * 8 + (lane & 3) * 2;
        size_t i0 = (bbase + gi0) * (size_t)HDn + col;
        size_t i1 = (bbase + gi1) * (size_t)HDn + col;
        uint32_t hp, lp;
        splitpair(accO[nf][0] * sc0, accO[nf][1] * sc0, hp, lp);
        *(uint32_t*)(aoh + i0) = hp;
        *(uint32_t*)(aol + i0) = lp;
        splitpair(accO[nf][2] * sc1, accO[nf][3] * sc1, hp, lp);
        *(uint32_t*)(aoh + i1) = hp;
        *(uint32_t*)(aol + i1) = lp;
    }
}

// ---------------------------------------------------------------------------
extern "C" void kernel_launch(void* const* d_in, const int* in_sizes, int n_in,
                              void* d_out, int out_size)
{
    const float* tokens = (const float*)d_in[0];
    const float* vres   = (const float*)d_in[1];
    const float* Wq     = (const float*)d_in[2];
    const float* Wkv    = (const float*)d_in[3];
    const float* Wout   = (const float*)d_in[4];
    const float* Wgate  = (const float*)d_in[5];
    const float* Wmix   = (const float*)d_in[6];
    float* out = (float*)d_out;

    float *pmix, *pgate;
    ush *tkh, *tkl, *aoh, *aol, *wah, *wal, *woh, *wol;
    ush *qsh, *qsl, *ksh, *ksl, *vsh, *vsl;
    cudaGetSymbolAddress((void**)&pmix, g_mix);
    cudaGetSymbolAddress((void**)&pgate,g_gate);
    cudaGetSymbolAddress((void**)&tkh,  g_tokh);
    cudaGetSymbolAddress((void**)&tkl,  g_tokl);
    cudaGetSymbolAddress((void**)&aoh,  g_aoh);
    cudaGetSymbolAddress((void**)&aol,  g_aol);
    cudaGetSymbolAddress((void**)&wah,  g_wallh);
    cudaGetSymbolAddress((void**)&wal,  g_walll);
    cudaGetSymbolAddress((void**)&woh,  g_woh);
    cudaGetSymbolAddress((void**)&wol,  g_wol);
    cudaGetSymbolAddress((void**)&qsh,  g_qsh);
    cudaGetSymbolAddress((void**)&qsl,  g_qsl);
    cudaGetSymbolAddress((void**)&ksh,  g_ksh);
    cudaGetSymbolAddress((void**)&ksl,  g_ksl);
    cudaGetSymbolAddress((void**)&vsh,  g_vsh);
    cudaGetSymbolAddress((void**)&vsl,  g_vsl);

    cudaFuncSetAttribute(gemm_mma, cudaFuncAttributeMaxDynamicSharedMemorySize, GEMM_SMEM);
    cudaFuncSetAttribute(attn_mma, cudaFuncAttributeMaxDynamicSharedMemorySize, ATT_SMEM);

    // 1. splits: tokens; merged weight wall = [Wq rows | Wkv rows]; Wout
    convA<<<(Tn * DIMn / 4 + 255) / 256, 256>>>(tokens, tkh, tkl, Tn * DIMn / 4);
    convW<<<dim3(1024 / 32, 1024 / 32), dim3(32, 8)>>>(Wq,  wah,               wal,               1024, 1024);
    convW<<<dim3(2048 / 32, 1024 / 32), dim3(32, 8)>>>(Wkv, wah + 1024 * 1024, wal + 1024 * 1024, 1024, 2048);
    convW<<<dim3(1024 / 32, 1024 / 32), dim3(32, 8)>>>(Wout, woh, wol, 1024, 1024);

    // 2. mix / gate logits + sigmoid
    mixgate<<<64, 256>>>(tokens, Wmix, Wgate, pmix, pgate);

    // 3. merged QKV projection with fused rope / v-mix epilogue
    gemm_mma<<<dim3(24, 64), 256, GEMM_SMEM>>>(
        tkh, tkl, wah, wal, nullptr,
        qsh, qsl, ksh, ksl, vsh, vsl, vres, pmix, 1);

    // 4. windowed attention on tensor cores (+gate), writes ao splits
    attn_mma<<<dim3(Sn / 64, Hn, Bn), 128, ATT_SMEM>>>(
        qsh, qsl, ksh, ksl, vsh, vsl, pgate, aoh, aol);

    // 5. output projection into d_out
    gemm_mma<<<dim3(8, 64), 256, GEMM_SMEM>>>(
        aoh, aol, woh, wol, out,
        nullptr, nullptr, nullptr, nullptr, nullptr, nullptr, nullptr, nullptr, 0);
}

// round 8
// speedup vs baseline: 1.4124x; 1.4124x over previous
#include <cuda_runtime.h>
#include <cuda_bf16.h>
#include <cuda_fp16.h>
#include <math.h>
#include <stdint.h>

// Problem constants
#define Bn 4
#define Sn 2048
#define DIMn 1024
#define Hn 16
#define Dn 64
#define Tn (Bn*Sn)      // 8192 tokens
#define HDn 1024
#define WIN 512

typedef unsigned short ush;

// ---------------------------------------------------------------------------
// Scratch (device globals)
// ---------------------------------------------------------------------------
__device__ float g_mix[Tn*Hn];
__device__ float g_gate[Tn*Hn];

__device__ ush g_tokh[(size_t)Tn*DIMn];   // fp16 hi
__device__ ush g_tokl[(size_t)Tn*DIMn];   // fp16 lo
__device__ ush g_aoh[(size_t)Tn*HDn];     // fp16 hi
__device__ ush g_aol[(size_t)Tn*HDn];     // fp16 lo
__device__ ush g_wallh[3072*1024];        // fp16 single: [Wq|Wk|Wv]^T [N=3072,K=1024]
__device__ ush g_woh[1024*1024];          // fp16 single: Wout^T
// post-rope / post-vmix bf16 splits (attention operands)
__device__ ush g_qsh[(size_t)Tn*HDn];
__device__ ush g_qsl[(size_t)Tn*HDn];
__device__ ush g_ksh[(size_t)Tn*HDn];
__device__ ush g_ksl[(size_t)Tn*HDn];
__device__ ush g_vsh[(size_t)Tn*HDn];
__device__ ush g_vsl[(size_t)Tn*HDn];

// ---------------------------------------------------------------------------
// Helpers (base sm_103 target — mma.sync / ldmatrix / cp.async, NO tcgen05)
// ---------------------------------------------------------------------------
__device__ __forceinline__ uint32_t smem_u32(const void* p) {
    uint32_t a;
    asm("{ .reg .u64 t; cvta.to.shared.u64 t, %1; cvt.u32.u64 %0, t; }" : "=r"(a) : "l"(p));
    return a;
}
__device__ __forceinline__ void ldsm4(uint32_t* r, uint32_t addr) {
    asm volatile("ldmatrix.sync.aligned.m8n8.x4.shared.b16 {%0,%1,%2,%3}, [%4];"
                 : "=r"(r[0]), "=r"(r[1]), "=r"(r[2]), "=r"(r[3]) : "r"(addr));
}
__device__ __forceinline__ void ldsm4t(uint32_t* r, uint32_t addr) {
    asm volatile("ldmatrix.sync.aligned.m8n8.x4.trans.shared.b16 {%0,%1,%2,%3}, [%4];"
                 : "=r"(r[0]), "=r"(r[1]), "=r"(r[2]), "=r"(r[3]) : "r"(addr));
}
// bf16 MMA (attention)
__device__ __forceinline__ void mma16816(float* d, const uint32_t* a, const uint32_t* b) {
    asm volatile("mma.sync.aligned.m16n8k16.row.col.f32.bf16.bf16.f32 "
                 "{%0,%1,%2,%3},{%4,%5,%6,%7},{%8,%9},{%0,%1,%2,%3};"
                 : "+f"(d[0]), "+f"(d[1]), "+f"(d[2]), "+f"(d[3])
                 : "r"(a[0]), "r"(a[1]), "r"(a[2]), "r"(a[3]),
                   "r"(b[0]), "r"(b[1]));
}
// fp16 MMA (projection GEMMs)
__device__ __forceinline__ void mma16816h(float* d, const uint32_t* a, const uint32_t* b) {
    asm volatile("mma.sync.aligned.m16n8k16.row.col.f32.f16.f16.f32 "
                 "{%0,%1,%2,%3},{%4,%5,%6,%7},{%8,%9},{%0,%1,%2,%3};"
                 : "+f"(d[0]), "+f"(d[1]), "+f"(d[2]), "+f"(d[3])
                 : "r"(a[0]), "r"(a[1]), "r"(a[2]), "r"(a[3]),
                   "r"(b[0]), "r"(b[1]));
}
__device__ __forceinline__ void cp16(uint32_t smem, const void* g) {
    asm volatile("cp.async.cg.shared.global [%0], [%1], 16;" :: "r"(smem), "l"(g));
}
// pack two fp32 -> bf16x2 (first arg -> low 16 bits)
__device__ __forceinline__ uint32_t packbf(float lo, float hi) {
    uint32_t r;
    asm("cvt.rn.bf16x2.f32 %0, %1, %2;" : "=r"(r) : "f"(hi), "f"(lo));
    return r;
}
__device__ __forceinline__ void splitpair(float y0, float y1, uint32_t& hp, uint32_t& lp) {
    hp = packbf(y0, y1);
    lp = packbf(y0 - __uint_as_float(hp << 16),
                y1 - __uint_as_float(hp & 0xFFFF0000u));
}
// fp16 pair split
__device__ __forceinline__ void splitpairh(float y0, float y1, uint32_t& hp, uint32_t& lp) {
    __half2 h = __floats2half2_rn(y0, y1);
    hp = *reinterpret_cast<uint32_t*>(&h);
    __half2 l = __floats2half2_rn(y0 - __low2float(h), y1 - __high2float(h));
    lp = *reinterpret_cast<uint32_t*>(&l);
}

// ---------------------------------------------------------------------------
// fp32 -> fp16 hi/lo split (elementwise)
// ---------------------------------------------------------------------------
__global__ void convA(const float* __restrict__ x, ush* __restrict__ h,
                      ush* __restrict__ l, int n4)
{
    int i = blockIdx.x * blockDim.x + threadIdx.x;
    if (i >= n4) return;
    float4 v = ((const float4*)x)[i];
    float vs[4] = {v.x, v.y, v.z, v.w};
    ush hs[4], ls[4];
#pragma unroll
    for (int j = 0; j < 4; j++) {
        __half hb = __float2half_rn(vs[j]);
        float r = vs[j] - __half2float(hb);
        __half lb = __float2half_rn(r);
        hs[j] = *reinterpret_cast<ush*>(&hb);
        ls[j] = *reinterpret_cast<ush*>(&lb);
    }
    ((ushort4*)h)[i] = make_ushort4(hs[0], hs[1], hs[2], hs[3]);
    ((ushort4*)l)[i] = make_ushort4(ls[0], ls[1], ls[2], ls[3]);
}

// W [K,N] fp32 -> W^T [N,K] fp16 single (transpose via smem)
__global__ void convW(const float* __restrict__ W, ush* __restrict__ Th, int K, int N)
{
    __shared__ float t[32][33];
    int n0 = blockIdx.x * 32, k0 = blockIdx.y * 32;
    int tx = threadIdx.x, ty = threadIdx.y;   // blockDim (32, 8)
#pragma unroll
    for (int r = 0; r < 4; r++)
        t[ty + 8 * r][tx] = W[(size_t)(k0 + ty + 8 * r) * N + n0 + tx];
    __syncthreads();
#pragma unroll
    for (int r = 0; r < 4; r++) {
        float v = t[tx][ty + 8 * r];
        __half hb = __float2half_rn(v);
        Th[(size_t)(n0 + ty + 8 * r) * K + k0 + tx] = *reinterpret_cast<ush*>(&hb);
    }
}

// ---------------------------------------------------------------------------
// fp16 2-term GEMM: C = (Ah+Al) @ Bh^T. CTA 128x128, 256 thr, 8 warps (4m x 2n),
// warp tile 32x64, K-chunk 32, double-buffered cp.async (round-4 structure).
// mode 0: fp32 C store. mode 1: fused QKV epilogue (rope / v-mix -> bf16 splits).
// ---------------------------------------------------------------------------
#define PADE 40
#define KIND_ELEMS (128*PADE)            // 5120 ush = 10KB
#define STAGE_ELEMS (3*KIND_ELEMS)       // Ah, Al, Bh
#define GEMM_SMEM (2*STAGE_ELEMS*2)      // 61440 B

__global__ void __launch_bounds__(256, 2) gemm_mma(
    const ush* __restrict__ Ah, const ush* __restrict__ Al,
    const ush* __restrict__ Bh,
    float* __restrict__ C,
    ush* __restrict__ qh, ush* __restrict__ ql,
    ush* __restrict__ kh, ush* __restrict__ kl,
    ush* __restrict__ vh, ush* __restrict__ vl,
    const float* __restrict__ vres, const float* __restrict__ mix,
    int mode)
{
    extern __shared__ ush sh[];
    const int tid  = threadIdx.x;
    const int wid  = tid >> 5, lane = tid & 31;
    const int brow = blockIdx.y * 128, bcol = blockIdx.x * 128;
    const int wm   = (wid & 3) * 32;
    const int wn   = (wid >> 2) * 64;
    const int K    = 1024;

    const uint32_t sbase = smem_u32(sh);

    float acc[2][8][4];
#pragma unroll
    for (int i = 0; i < 2; i++)
#pragma unroll
        for (int j = 0; j < 8; j++)
#pragma unroll
            for (int k = 0; k < 4; k++) acc[i][j][k] = 0.f;

    const ush* srcs[3] = {Ah, Al, Bh};
    const int rbase[3] = {brow, brow, bcol};

    auto cp_chunk = [&](int k0, int buf) {
#pragma unroll
        for (int kind = 0; kind < 3; kind++) {
#pragma unroll
            for (int half = 0; half < 2; half++) {
                int e = tid + half * 256;          // 0..511
                int row = e >> 2, ce = (e & 3) * 8;
                const ush* g = srcs[kind] + (size_t)(rbase[kind] + row) * K + k0 + ce;
                uint32_t d = sbase + (uint32_t)(buf * STAGE_ELEMS + kind * KIND_ELEMS +
                                                row * PADE + ce) * 2;
                cp16(d, g);
            }
        }
        asm volatile("cp.async.commit_group;" ::: "memory");
    };

    cp_chunk(0, 0);

    for (int c = 0; c < 32; c++) {
        int buf = c & 1;
        if (c < 31) {
            cp_chunk((c + 1) * 32, buf ^ 1);
            asm volatile("cp.async.wait_group 1;" ::: "memory");
        } else {
            asm volatile("cp.async.wait_group 0;" ::: "memory");
        }
        __syncthreads();

        uint32_t abase = sbase + (uint32_t)buf * STAGE_ELEMS * 2;

#pragma unroll
        for (int ksub = 0; ksub < 2; ksub++) {
            uint32_t a[2][2][4];
            {
                int arow = wm + (lane & 15);
                int acol = ksub * 16 + (lane >> 4) * 8;
#pragma unroll
                for (int sp = 0; sp < 2; sp++)
#pragma unroll
                    for (int ms = 0; ms < 2; ms++)
                        ldsm4(a[sp][ms], abase + (uint32_t)(sp * KIND_ELEMS +
                              (arow + ms * 16) * PADE + acol) * 2);
            }
            uint32_t b[8][2];
            {
                int bn = (lane & 7) | ((lane >> 1) & 8);
                int bk = ksub * 16 + ((lane >> 3) & 1) * 8;
#pragma unroll
                for (int g = 0; g < 4; g++) {
                    uint32_t r[4];
                    ldsm4(r, abase + (uint32_t)(2 * KIND_ELEMS +
                          (wn + g * 16 + bn) * PADE + bk) * 2);
                    b[2 * g][0]     = r[0]; b[2 * g][1]     = r[1];
                    b[2 * g + 1][0] = r[2]; b[2 * g + 1][1] = r[3];
                }
            }
#pragma unroll
            for (int ms = 0; ms < 2; ms++)
#pragma unroll
                for (int nf = 0; nf < 8; nf++) {
                    mma16816h(acc[ms][nf], a[0][ms], b[nf]);   // Ah * B
                    mma16816h(acc[ms][nf], a[1][ms], b[nf]);   // Al * B
                }
        }
        __syncthreads();
    }

    if (mode == 0) {
#pragma unroll
        for (int ms = 0; ms < 2; ms++) {
            int r0 = brow + wm + ms * 16 + (lane >> 2);
#pragma unroll
            for (int nf = 0; nf < 8; nf++) {
                int cc = bcol + wn + nf * 8 + 2 * (lane & 3);
                *(float2*)(C + (size_t)r0 * 1024 + cc)       = make_float2(acc[ms][nf][0], acc[ms][nf][1]);
                *(float2*)(C + (size_t)(r0 + 8) * 1024 + cc) = make_float2(acc[ms][nf][2], acc[ms][nf][3]);
            }
        }
        return;
    }

    // fused QKV epilogue: seg 0=q (rope+scale), 1=k (rope), 2=v (mix lerp)
    const int seg  = bcol >> 10;
    const int colb = (bcol & 1023) + wn + 2 * (lane & 3);
    ush* dh = (seg == 0) ? qh : (seg == 1) ? kh : vh;
    ush* dl = (seg == 0) ? ql : (seg == 1) ? kl : vl;
    const float qscale = (seg == 0) ? 0.125f : 1.0f;
    const float L2F = 13.2877123795494f / 32.0f;   // log2(10000)/32

#pragma unroll
    for (int ms = 0; ms < 2; ms++) {
        int r0 = brow + wm + ms * 16 + (lane >> 2);
#pragma unroll
        for (int half = 0; half < 2; half++) {
            int row = r0 + half * 8;
            int s = row & (Sn - 1);
            int bb = row >> 11;
#pragma unroll
            for (int nf = 0; nf < 8; nf++) {
                float x0 = acc[ms][nf][half * 2 + 0];
                float x1 = acc[ms][nf][half * 2 + 1];
                int colc = colb + nf * 8;
                float y0, y1;
                if (seg < 2) {
                    int i = (colc & 63) >> 1;
                    float inv = exp2f(-(float)i * L2F);
                    float ang = (float)s * inv;
                    float sn, cs;
                    sincosf(ang, &sn, &cs);
                    y0 = (x0 * cs - x1 * sn) * qscale;
                    y1 = (x1 * cs + x0 * sn) * qscale;
                } else {
                    int hh = (colc & 1023) >> 6;
                    int d  = colc & 63;
                    float m = mix[row * Hn + hh];
                    const float* rp = vres + (((size_t)bb * Hn + hh) * Sn + s) * Dn + d;
                    float2 rr = *(const float2*)rp;
                    y0 = x0 + (rr.x - x0) * m;
                    y1 = x1 + (rr.y - x1) * m;
                }
                uint32_t hp, lp;
                splitpair(y0, y1, hp, lp);   // bf16 splits for attention
                size_t o = (size_t)row * 1024 + colc;
                *(uint32_t*)(dh + o) = hp;
                *(uint32_t*)(dl + o) = lp;
            }
        }
    }
}

// ---------------------------------------------------------------------------
// mix/gate: (8192 x 1024) @ [Wmix | Wgate] (1024 x 32), sigmoid epilogue.
// ---------------------------------------------------------------------------
__global__ void __launch_bounds__(256) mixgate(
    const float* __restrict__ tokens, const float* __restrict__ Wmix,
    const float* __restrict__ Wgate, float* __restrict__ gmix,
    float* __restrict__ ggate)
{
    __shared__ float Ts[128][65];
    __shared__ float Ws[64][32];

    const int tid  = threadIdx.x;
    const int row0 = blockIdx.x * 128;
    const int r  = tid >> 1;
    const int cg = (tid & 1) << 4;

    float acc[16];
#pragma unroll
    for (int c = 0; c < 16; c++) acc[c] = 0.f;

    for (int k0 = 0; k0 < 1024; k0 += 64) {
#pragma unroll
        for (int u = 0; u < 8; u++) {
            int fi = tid + u * 256;
            int rr = fi >> 4;
            int cc = (fi & 15) << 2;
            float4 x = *(const float4*)(tokens + (size_t)(row0 + rr) * 1024 + k0 + cc);
            Ts[rr][cc] = x.x; Ts[rr][cc + 1] = x.y; Ts[rr][cc + 2] = x.z; Ts[rr][cc + 3] = x.w;
        }
#pragma unroll
        for (int u = 0; u < 8; u++) {
            int fi = tid + u * 256;
            int rr = fi >> 5;
            int cc = fi & 31;
            Ws[rr][cc] = (cc < 16) ? Wmix[(k0 + rr) * 16 + cc]
                                   : Wgate[(k0 + rr) * 16 + (cc - 16)];
        }
        __syncthreads();
        for (int kk = 0; kk < 64; kk++) {
            float a = Ts[r][kk];
#pragma unroll
            for (int c = 0; c < 16; c++) acc[c] += a * Ws[kk][cg + c];
        }
        __syncthreads();
    }

    const int t = row0 + r;
#pragma unroll
    for (int c = 0; c < 16; c++) {
        float sg = 1.0f / (1.0f + expf(-acc[c]));
        int col = cg + c;
        if (col < 16) gmix[t * 16 + col] = sg;
        else          ggate[t * 16 + (col - 16)] = sg;
    }
}

// ---------------------------------------------------------------------------
// Sliding-window flash attention, HMMA bf16x3, online softmax in registers.
// Epilogue now writes fp16 splits (consumed by the fp16 Wout GEMM).
// ---------------------------------------------------------------------------
#define APAD 72
#define ATT_SMEM (6*64*APAD*2)

__global__ void __launch_bounds__(128) attn_mma(
    const ush* __restrict__ qh, const ush* __restrict__ ql,
    const ush* __restrict__ kh, const ush* __restrict__ kl,
    const ush* __restrict__ vh, const ush* __restrict__ vl,
    const float* __restrict__ gate,
    ush* __restrict__ aoh, ush* __restrict__ aol)
{
    extern __shared__ ush smA[];
    ush* Qh = smA;
    ush* Ql = Qh + 64 * APAD;
    ush* Kh = Ql + 64 * APAD;
    ush* Kl = Kh + 64 * APAD;
    ush* Vh = Kl + 64 * APAD;
    ush* Vl = Vh + 64 * APAD;

    const int b = blockIdx.z, h = blockIdx.y, q0 = blockIdx.x * 64;
    const int tid = threadIdx.x, wid = tid >> 5, lane = tid & 31;
    const int wm = wid * 16;
    const size_t bbase = (size_t)b * Sn;
    const int hoff = h * Dn;

#pragma unroll
    for (int i = 0; i < 4; i++) {
        int e = tid + i * 128;
        int row = e >> 3, c = (e & 7) * 8;
        size_t g = (bbase + q0 + row) * (size_t)HDn + hoff + c;
        *(uint4*)(Qh + row * APAD + c) = *(const uint4*)(qh + g);
        *(uint4*)(Ql + row * APAD + c) = *(const uint4*)(ql + g);
    }
    __syncthreads();

    uint32_t qfh[4][4], qfl[4][4];
    {
        uint32_t qb = smem_u32(Qh), qbl = smem_u32(Ql);
        int arow = wm + (lane & 15);
        int ac0  = (lane >> 4) * 8;
#pragma unroll
        for (int ks = 0; ks < 4; ks++) {
            ldsm4(qfh[ks], qb  + (arow * APAD + ks * 16 + ac0) * 2);
            ldsm4(qfl[ks], qbl + (arow * APAD + ks * 16 + ac0) * 2);
        }
    }

    float mi0 = -1e30f, mi1 = -1e30f, li0 = 0.f, li1 = 0.f;
    float accO[8][4];
#pragma unroll
    for (int i = 0; i < 8; i++)
#pragma unroll
        for (int j = 0; j < 4; j++) accO[i][j] = 0.f;

    const int jt_lo = (q0 >= WIN) ? ((q0 - WIN) >> 6) : 0;
    const int jt_hi = q0 >> 6;
    const int gi0 = q0 + wm + (lane >> 2);
    const int gi1 = gi0 + 8;

    const uint32_t kb  = smem_u32(Kh), kbl = smem_u32(Kl);
    const uint32_t vb  = smem_u32(Vh), vbl = smem_u32(Vl);
    const int bn  = (lane & 7) | ((lane >> 1) & 8);
    const int bk8 = ((lane >> 3) & 1) * 8;
    const int vr0 = lane & 15;
    const int vc8 = (lane >> 4) * 8;

    for (int jt = jt_lo; jt <= jt_hi; jt++) {
        const int j0 = jt * 64;
#pragma unroll
        for (int i = 0; i < 4; i++) {
            int e = tid + i * 128;
            int row = e >> 3, c = (e & 7) * 8;
            size_t g = (bbase + j0 + row) * (size_t)HDn + hoff + c;
            *(uint4*)(Kh + row * APAD + c) = *(const uint4*)(kh + g);
            *(uint4*)(Kl + row * APAD + c) = *(const uint4*)(kl + g);
            *(uint4*)(Vh + row * APAD + c) = *(const uint4*)(vh + g);
            *(uint4*)(Vl + row * APAD + c) = *(const uint4*)(vl + g);
        }
        __syncthreads();

        float s[8][4];
#pragma unroll
        for (int i = 0; i < 8; i++)
#pragma unroll
            for (int j = 0; j < 4; j++) s[i][j] = 0.f;

#pragma unroll
        for (int ks = 0; ks < 4; ks++) {
#pragma unroll
            for (int g2 = 0; g2 < 4; g2++) {
                uint32_t off = (uint32_t)(((g2 * 16 + bn) * APAD + ks * 16 + bk8) * 2);
                uint32_t rh[4], rl[4];
                ldsm4(rh, kb  + off);
                ldsm4(rl, kbl + off);
                uint32_t bh0[2] = {rh[0], rh[1]}, bh1[2] = {rh[2], rh[3]};
                uint32_t bl0[2] = {rl[0], rl[1]}, bl1[2] = {rl[2], rl[3]};
                mma16816(s[2*g2],   qfh[ks], bh0);
                mma16816(s[2*g2],   qfh[ks], bl0);
                mma16816(s[2*g2],   qfl[ks], bh0);
                mma16816(s[2*g2+1], qfh[ks], bh1);
                mma16816(s[2*g2+1], qfh[ks], bl1);
                mma16816(s[2*g2+1], qfl[ks], bh1);
            }
        }

        if (jt == jt_hi || (jt == jt_lo && q0 >= WIN)) {
#pragma unroll
            for (int nf = 0; nf < 8; nf++) {
                int cbase = j0 + nf * 8 + (lane & 3) * 2;
#pragma unroll
                for (int jj = 0; jj < 2; jj++) {
                    int gj = cbase + jj;
                    int d0 = gi0 - gj, d1 = gi1 - gj;
                    if (d0 < 0 || d0 > WIN) s[nf][jj]     = -1e30f;
                    if (d1 < 0 || d1 > WIN) s[nf][2 + jj] = -1e30f;
                }
            }
        }

        float mt0 = -1e30f, mt1 = -1e30f;
#pragma unroll
        for (int nf = 0; nf < 8; nf++) {
            mt0 = fmaxf(mt0, fmaxf(s[nf][0], s[nf][1]));
            mt1 = fmaxf(mt1, fmaxf(s[nf][2], s[nf][3]));
        }
        mt0 = fmaxf(mt0, __shfl_xor_sync(0xffffffffu, mt0, 1));
        mt0 = fmaxf(mt0, __shfl_xor_sync(0xffffffffu, mt0, 2));
        mt1 = fmaxf(mt1, __shfl_xor_sync(0xffffffffu, mt1, 1));
        mt1 = fmaxf(mt1, __shfl_xor_sync(0xffffffffu, mt1, 2));

        float mn0 = fmaxf(mi0, mt0), mn1 = fmaxf(mi1, mt1);
        float f0 = __expf(mi0 - mn0), f1 = __expf(mi1 - mn1);
        mi0 = mn0; mi1 = mn1;

        float su0 = 0.f, su1 = 0.f;
#pragma unroll
        for (int nf = 0; nf < 8; nf++) {
            s[nf][0] = __expf(s[nf][0] - mn0);
            s[nf][1] = __expf(s[nf][1] - mn0);
            s[nf][2] = __expf(s[nf][2] - mn1);
            s[nf][3] = __expf(s[nf][3] - mn1);
            su0 += s[nf][0] + s[nf][1];
            su1 += s[nf][2] + s[nf][3];
        }
        su0 += __shfl_xor_sync(0xffffffffu, su0, 1);
        su0 += __shfl_xor_sync(0xffffffffu, su0, 2);
        su1 += __shfl_xor_sync(0xffffffffu, su1, 1);
        su1 += __shfl_xor_sync(0xffffffffu, su1, 2);
        li0 = li0 * f0 + su0;
        li1 = li1 * f1 + su1;
#pragma unroll
        for (int nf = 0; nf < 8; nf++) {
            accO[nf][0] *= f0; accO[nf][1] *= f0;
            accO[nf][2] *= f1; accO[nf][3] *= f1;
        }

#pragma unroll
        for (int ks = 0; ks < 4; ks++) {
            uint32_t ph[4], pl[4];
            const float* p0 = s[2 * ks];
            const float* p1 = s[2 * ks + 1];
            splitpair(p0[0], p0[1], ph[0], pl[0]);
            splitpair(p0[2], p0[3], ph[1], pl[1]);
            splitpair(p1[0], p1[1], ph[2], pl[2]);
            splitpair(p1[2], p1[3], ph[3], pl[3]);
#pragma unroll
            for (int g2 = 0; g2 < 4; g2++) {
                uint32_t off = (uint32_t)(((ks * 16 + vr0) * APAD + g2 * 16 + vc8) * 2);
                uint32_t rh[4], rl[4];
                ldsm4t(rh, vb  + off);
                ldsm4t(rl, vbl + off);
                uint32_t bh0[2] = {rh[0], rh[1]}, bh1[2] = {rh[2], rh[3]};
                uint32_t bl0[2] = {rl[0], rl[1]}, bl1[2] = {rl[2], rl[3]};
                mma16816(accO[2*g2],   ph, bh0);
                mma16816(accO[2*g2],   ph, bl0);
                mma16816(accO[2*g2],   pl, bh0);
                mma16816(accO[2*g2+1], ph, bh1);
                mma16816(accO[2*g2+1], ph, bl1);
                mma16816(accO[2*g2+1], pl, bh1);
            }
        }
        __syncthreads();
    }

    float g0 = gate[(bbase + gi0) * Hn + h];
    float g1 = gate[(bbase + gi1) * Hn + h];
    float sc0 = g0 / li0, sc1 = g1 / li1;
#pragma unroll
    for (int nf = 0; nf < 8; nf++) {
        int col = hoff + nf * 8 + (lane & 3) * 2;
        size_t i0 = (bbase + gi0) * (size_t)HDn + col;
        size_t i1 = (bbase + gi1) * (size_t)HDn + col;
        uint32_t hp, lp;
        splitpairh(accO[nf][0] * sc0, accO[nf][1] * sc0, hp, lp);  // fp16 splits
        *(uint32_t*)(aoh + i0) = hp;
        *(uint32_t*)(aol + i0) = lp;
        splitpairh(accO[nf][2] * sc1, accO[nf][3] * sc1, hp, lp);
        *(uint32_t*)(aoh + i1) = hp;
        *(uint32_t*)(aol + i1) = lp;
    }
}

// ---------------------------------------------------------------------------
extern "C" void kernel_launch(void* const* d_in, const int* in_sizes, int n_in,
                              void* d_out, int out_size)
{
    const float* tokens = (const float*)d_in[0];
    const float* vres   = (const float*)d_in[1];
    const float* Wq     = (const float*)d_in[2];
    const float* Wkv    = (const float*)d_in[3];
    const float* Wout   = (const float*)d_in[4];
    const float* Wgate  = (const float*)d_in[5];
    const float* Wmix   = (const float*)d_in[6];
    float* out = (float*)d_out;

    float *pmix, *pgate;
    ush *tkh, *tkl, *aoh, *aol, *wah, *woh;
    ush *qsh, *qsl, *ksh, *ksl, *vsh, *vsl;
    cudaGetSymbolAddress((void**)&pmix, g_mix);
    cudaGetSymbolAddress((void**)&pgate,g_gate);
    cudaGetSymbolAddress((void**)&tkh,  g_tokh);
    cudaGetSymbolAddress((void**)&tkl,  g_tokl);
    cudaGetSymbolAddress((void**)&aoh,  g_aoh);
    cudaGetSymbolAddress((void**)&aol,  g_aol);
    cudaGetSymbolAddress((void**)&wah,  g_wallh);
    cudaGetSymbolAddress((void**)&woh,  g_woh);
    cudaGetSymbolAddress((void**)&qsh,  g_qsh);
    cudaGetSymbolAddress((void**)&qsl,  g_qsl);
    cudaGetSymbolAddress((void**)&ksh,  g_ksh);
    cudaGetSymbolAddress((void**)&ksl,  g_ksl);
    cudaGetSymbolAddress((void**)&vsh,  g_vsh);
    cudaGetSymbolAddress((void**)&vsl,  g_vsl);

    cudaFuncSetAttribute(gemm_mma, cudaFuncAttributeMaxDynamicSharedMemorySize, GEMM_SMEM);
    cudaFuncSetAttribute(attn_mma, cudaFuncAttributeMaxDynamicSharedMemorySize, ATT_SMEM);

    // 1. splits: tokens (fp16 hi/lo); weights single fp16 transposed
    convA<<<(Tn * DIMn / 4 + 255) / 256, 256>>>(tokens, tkh, tkl, Tn * DIMn / 4);
    convW<<<dim3(1024 / 32, 1024 / 32), dim3(32, 8)>>>(Wq,  wah,               1024, 1024);
    convW<<<dim3(2048 / 32, 1024 / 32), dim3(32, 8)>>>(Wkv, wah + 1024 * 1024, 1024, 2048);
    convW<<<dim3(1024 / 32, 1024 / 32), dim3(32, 8)>>>(Wout, woh, 1024, 1024);

    // 2. mix / gate logits + sigmoid
    mixgate<<<64, 256>>>(tokens, Wmix, Wgate, pmix, pgate);

    // 3. merged QKV projection (fp16 2-term) with fused rope / v-mix epilogue
    gemm_mma<<<dim3(24, 64), 256, GEMM_SMEM>>>(
        tkh, tkl, wah, nullptr,
        qsh, qsl, ksh, ksl, vsh, vsl, vres, pmix, 1);

    // 4. windowed attention (bf16x3) + gate, writes fp16 ao splits
    attn_mma<<<dim3(Sn / 64, Hn, Bn), 128, ATT_SMEM>>>(
        qsh, qsl, ksh, ksl, vsh, vsl, pgate, aoh, aol);

    // 5. output projection (fp16 2-term) into d_out
    gemm_mma<<<dim3(8, 64), 256, GEMM_SMEM>>>(
        aoh, aol, woh, out,
        nullptr, nullptr, nullptr, nullptr, nullptr, nullptr, nullptr, nullptr, 0);
}

// round 9
// speedup vs baseline: 1.5035x; 1.0645x over previous
#include <cuda_runtime.h>
#include <cuda_bf16.h>
#include <cuda_fp16.h>
#include <math.h>
#include <stdint.h>

// Problem constants
#define Bn 4
#define Sn 2048
#define DIMn 1024
#define Hn 16
#define Dn 64
#define Tn (Bn*Sn)      // 8192 tokens
#define HDn 1024
#define WIN 512

typedef unsigned short ush;

// ---------------------------------------------------------------------------
// Scratch (device globals)
// ---------------------------------------------------------------------------
__device__ float g_mix[Tn*Hn];
__device__ float g_gate[Tn*Hn];

__device__ ush g_tokh[(size_t)Tn*DIMn];   // fp16 hi
__device__ ush g_tokl[(size_t)Tn*DIMn];   // fp16 lo
__device__ ush g_aoh[(size_t)Tn*HDn];     // fp16 hi
__device__ ush g_aol[(size_t)Tn*HDn];     // fp16 lo
__device__ ush g_wallh[3072*1024];        // fp16 single: [Wq|Wk|Wv]^T [N=3072,K=1024]
__device__ ush g_woh[1024*1024];          // fp16 single: Wout^T
// attention operands: q fp16 hi/lo, k/v fp16 single
__device__ ush g_qsh[(size_t)Tn*HDn];
__device__ ush g_qsl[(size_t)Tn*HDn];
__device__ ush g_ks[(size_t)Tn*HDn];
__device__ ush g_vs[(size_t)Tn*HDn];

// ---------------------------------------------------------------------------
// Helpers (base sm_103 target — mma.sync / ldmatrix / cp.async, NO tcgen05)
// ---------------------------------------------------------------------------
__device__ __forceinline__ uint32_t smem_u32(const void* p) {
    uint32_t a;
    asm("{ .reg .u64 t; cvta.to.shared.u64 t, %1; cvt.u32.u64 %0, t; }" : "=r"(a) : "l"(p));
    return a;
}
__device__ __forceinline__ void ldsm4(uint32_t* r, uint32_t addr) {
    asm volatile("ldmatrix.sync.aligned.m8n8.x4.shared.b16 {%0,%1,%2,%3}, [%4];"
                 : "=r"(r[0]), "=r"(r[1]), "=r"(r[2]), "=r"(r[3]) : "r"(addr));
}
__device__ __forceinline__ void ldsm4t(uint32_t* r, uint32_t addr) {
    asm volatile("ldmatrix.sync.aligned.m8n8.x4.trans.shared.b16 {%0,%1,%2,%3}, [%4];"
                 : "=r"(r[0]), "=r"(r[1]), "=r"(r[2]), "=r"(r[3]) : "r"(addr));
}
// fp16 MMA (all matmuls)
__device__ __forceinline__ void mma16816h(float* d, const uint32_t* a, const uint32_t* b) {
    asm volatile("mma.sync.aligned.m16n8k16.row.col.f32.f16.f16.f32 "
                 "{%0,%1,%2,%3},{%4,%5,%6,%7},{%8,%9},{%0,%1,%2,%3};"
                 : "+f"(d[0]), "+f"(d[1]), "+f"(d[2]), "+f"(d[3])
                 : "r"(a[0]), "r"(a[1]), "r"(a[2]), "r"(a[3]),
                   "r"(b[0]), "r"(b[1]));
}
__device__ __forceinline__ void cp16(uint32_t smem, const void* g) {
    asm volatile("cp.async.cg.shared.global [%0], [%1], 16;" :: "r"(smem), "l"(g));
}
// fp16 pair pack / split
__device__ __forceinline__ uint32_t packh(float y0, float y1) {
    __half2 h = __floats2half2_rn(y0, y1);
    return *reinterpret_cast<uint32_t*>(&h);
}
__device__ __forceinline__ void splitpairh(float y0, float y1, uint32_t& hp, uint32_t& lp) {
    __half2 h = __floats2half2_rn(y0, y1);
    hp = *reinterpret_cast<uint32_t*>(&h);
    __half2 l = __floats2half2_rn(y0 - __low2float(h), y1 - __high2float(h));
    lp = *reinterpret_cast<uint32_t*>(&l);
}

// ---------------------------------------------------------------------------
// fp32 -> fp16 hi/lo split (elementwise)
// ---------------------------------------------------------------------------
__global__ void convA(const float* __restrict__ x, ush* __restrict__ h,
                      ush* __restrict__ l, int n4)
{
    int i = blockIdx.x * blockDim.x + threadIdx.x;
    if (i >= n4) return;
    float4 v = ((const float4*)x)[i];
    float vs[4] = {v.x, v.y, v.z, v.w};
    ush hs[4], ls[4];
#pragma unroll
    for (int j = 0; j < 4; j++) {
        __half hb = __float2half_rn(vs[j]);
        float r = vs[j] - __half2float(hb);
        __half lb = __float2half_rn(r);
        hs[j] = *reinterpret_cast<ush*>(&hb);
        ls[j] = *reinterpret_cast<ush*>(&lb);
    }
    ((ushort4*)h)[i] = make_ushort4(hs[0], hs[1], hs[2], hs[3]);
    ((ushort4*)l)[i] = make_ushort4(ls[0], ls[1], ls[2], ls[3]);
}

// W [K,N] fp32 -> W^T [N,K] fp16 single (transpose via smem)
__global__ void convW(const float* __restrict__ W, ush* __restrict__ Th, int K, int N)
{
    __shared__ float t[32][33];
    int n0 = blockIdx.x * 32, k0 = blockIdx.y * 32;
    int tx = threadIdx.x, ty = threadIdx.y;   // blockDim (32, 8)
#pragma unroll
    for (int r = 0; r < 4; r++)
        t[ty + 8 * r][tx] = W[(size_t)(k0 + ty + 8 * r) * N + n0 + tx];
    __syncthreads();
#pragma unroll
    for (int r = 0; r < 4; r++) {
        float v = t[tx][ty + 8 * r];
        __half hb = __float2half_rn(v);
        Th[(size_t)(n0 + ty + 8 * r) * K + k0 + tx] = *reinterpret_cast<ush*>(&hb);
    }
}

// ---------------------------------------------------------------------------
// fp16 2-term GEMM: C = (Ah+Al) @ Bh^T. CTA 128x128, 256 thr, 8 warps (4m x 2n),
// warp tile 32x64, K-chunk 32, double-buffered cp.async.
// mode 0: fp32 C store. mode 1: fused QKV epilogue:
//   seg0 rope+scale -> q fp16 hi/lo; seg1 rope -> k fp16 single;
//   seg2 v-mix lerp -> v fp16 single.
// ---------------------------------------------------------------------------
#define PADE 40
#define KIND_ELEMS (128*PADE)            // 5120 ush = 10KB
#define STAGE_ELEMS (3*KIND_ELEMS)       // Ah, Al, Bh
#define GEMM_SMEM (2*STAGE_ELEMS*2)      // 61440 B

__global__ void __launch_bounds__(256, 2) gemm_mma(
    const ush* __restrict__ Ah, const ush* __restrict__ Al,
    const ush* __restrict__ Bh,
    float* __restrict__ C,
    ush* __restrict__ qh, ush* __restrict__ ql,
    ush* __restrict__ ks, ush* __restrict__ vs,
    const float* __restrict__ vres, const float* __restrict__ mix,
    int mode)
{
    extern __shared__ ush sh[];
    const int tid  = threadIdx.x;
    const int wid  = tid >> 5, lane = tid & 31;
    const int brow = blockIdx.y * 128, bcol = blockIdx.x * 128;
    const int wm   = (wid & 3) * 32;
    const int wn   = (wid >> 2) * 64;
    const int K    = 1024;

    const uint32_t sbase = smem_u32(sh);

    float acc[2][8][4];
#pragma unroll
    for (int i = 0; i < 2; i++)
#pragma unroll
        for (int j = 0; j < 8; j++)
#pragma unroll
            for (int k = 0; k < 4; k++) acc[i][j][k] = 0.f;

    const ush* srcs[3] = {Ah, Al, Bh};
    const int rbase[3] = {brow, brow, bcol};

    auto cp_chunk = [&](int k0, int buf) {
#pragma unroll
        for (int kind = 0; kind < 3; kind++) {
#pragma unroll
            for (int half = 0; half < 2; half++) {
                int e = tid + half * 256;
                int row = e >> 2, ce = (e & 3) * 8;
                const ush* g = srcs[kind] + (size_t)(rbase[kind] + row) * K + k0 + ce;
                uint32_t d = sbase + (uint32_t)(buf * STAGE_ELEMS + kind * KIND_ELEMS +
                                                row * PADE + ce) * 2;
                cp16(d, g);
            }
        }
        asm volatile("cp.async.commit_group;" ::: "memory");
    };

    cp_chunk(0, 0);

    for (int c = 0; c < 32; c++) {
        int buf = c & 1;
        if (c < 31) {
            cp_chunk((c + 1) * 32, buf ^ 1);
            asm volatile("cp.async.wait_group 1;" ::: "memory");
        } else {
            asm volatile("cp.async.wait_group 0;" ::: "memory");
        }
        __syncthreads();

        uint32_t abase = sbase + (uint32_t)buf * STAGE_ELEMS * 2;

#pragma unroll
        for (int ksub = 0; ksub < 2; ksub++) {
            uint32_t a[2][2][4];
            {
                int arow = wm + (lane & 15);
                int acol = ksub * 16 + (lane >> 4) * 8;
#pragma unroll
                for (int sp = 0; sp < 2; sp++)
#pragma unroll
                    for (int ms = 0; ms < 2; ms++)
                        ldsm4(a[sp][ms], abase + (uint32_t)(sp * KIND_ELEMS +
                              (arow + ms * 16) * PADE + acol) * 2);
            }
            uint32_t b[8][2];
            {
                int bn = (lane & 7) | ((lane >> 1) & 8);
                int bk = ksub * 16 + ((lane >> 3) & 1) * 8;
#pragma unroll
                for (int g = 0; g < 4; g++) {
                    uint32_t r[4];
                    ldsm4(r, abase + (uint32_t)(2 * KIND_ELEMS +
                          (wn + g * 16 + bn) * PADE + bk) * 2);
                    b[2 * g][0]     = r[0]; b[2 * g][1]     = r[1];
                    b[2 * g + 1][0] = r[2]; b[2 * g + 1][1] = r[3];
                }
            }
#pragma unroll
            for (int ms = 0; ms < 2; ms++)
#pragma unroll
                for (int nf = 0; nf < 8; nf++) {
                    mma16816h(acc[ms][nf], a[0][ms], b[nf]);   // Ah * B
                    mma16816h(acc[ms][nf], a[1][ms], b[nf]);   // Al * B
                }
        }
        __syncthreads();
    }

    if (mode == 0) {
#pragma unroll
        for (int ms = 0; ms < 2; ms++) {
            int r0 = brow + wm + ms * 16 + (lane >> 2);
#pragma unroll
            for (int nf = 0; nf < 8; nf++) {
                int cc = bcol + wn + nf * 8 + 2 * (lane & 3);
                *(float2*)(C + (size_t)r0 * 1024 + cc)       = make_float2(acc[ms][nf][0], acc[ms][nf][1]);
                *(float2*)(C + (size_t)(r0 + 8) * 1024 + cc) = make_float2(acc[ms][nf][2], acc[ms][nf][3]);
            }
        }
        return;
    }

    // fused QKV epilogue
    const int seg  = bcol >> 10;          // 0=q, 1=k, 2=v
    const int colb = (bcol & 1023) + wn + 2 * (lane & 3);
    const float qscale = (seg == 0) ? 0.125f : 1.0f;
    const float L2F = 13.2877123795494f / 32.0f;   // log2(10000)/32

#pragma unroll
    for (int ms = 0; ms < 2; ms++) {
        int r0 = brow + wm + ms * 16 + (lane >> 2);
#pragma unroll
        for (int half = 0; half < 2; half++) {
            int row = r0 + half * 8;
            int s = row & (Sn - 1);
            int bb = row >> 11;
#pragma unroll
            for (int nf = 0; nf < 8; nf++) {
                float x0 = acc[ms][nf][half * 2 + 0];
                float x1 = acc[ms][nf][half * 2 + 1];
                int colc = colb + nf * 8;
                size_t o = (size_t)row * 1024 + colc;
                if (seg < 2) {
                    int i = (colc & 63) >> 1;
                    float inv = exp2f(-(float)i * L2F);
                    float ang = (float)s * inv;
                    float sn, cs;
                    sincosf(ang, &sn, &cs);
                    float y0 = (x0 * cs - x1 * sn) * qscale;
                    float y1 = (x1 * cs + x0 * sn) * qscale;
                    if (seg == 0) {
                        uint32_t hp, lp;
                        splitpairh(y0, y1, hp, lp);
                        *(uint32_t*)(qh + o) = hp;
                        *(uint32_t*)(ql + o) = lp;
                    } else {
                        *(uint32_t*)(ks + o) = packh(y0, y1);
                    }
                } else {
                    int hh = (colc & 1023) >> 6;
                    int d  = colc & 63;
                    float m = mix[row * Hn + hh];
                    const float* rp = vres + (((size_t)bb * Hn + hh) * Sn + s) * Dn + d;
                    float2 rr = *(const float2*)rp;
                    float y0 = x0 + (rr.x - x0) * m;
                    float y1 = x1 + (rr.y - x1) * m;
                    *(uint32_t*)(vs + o) = packh(y0, y1);
                }
            }
        }
    }
}

// ---------------------------------------------------------------------------
// mix/gate: (8192 x 1024) @ [Wmix | Wgate] (1024 x 32), sigmoid epilogue.
// ---------------------------------------------------------------------------
__global__ void __launch_bounds__(256) mixgate(
    const float* __restrict__ tokens, const float* __restrict__ Wmix,
    const float* __restrict__ Wgate, float* __restrict__ gmix,
    float* __restrict__ ggate)
{
    __shared__ float Ts[128][65];
    __shared__ float Ws[64][32];

    const int tid  = threadIdx.x;
    const int row0 = blockIdx.x * 128;
    const int r  = tid >> 1;
    const int cg = (tid & 1) << 4;

    float acc[16];
#pragma unroll
    for (int c = 0; c < 16; c++) acc[c] = 0.f;

    for (int k0 = 0; k0 < 1024; k0 += 64) {
#pragma unroll
        for (int u = 0; u < 8; u++) {
            int fi = tid + u * 256;
            int rr = fi >> 4;
            int cc = (fi & 15) << 2;
            float4 x = *(const float4*)(tokens + (size_t)(row0 + rr) * 1024 + k0 + cc);
            Ts[rr][cc] = x.x; Ts[rr][cc + 1] = x.y; Ts[rr][cc + 2] = x.z; Ts[rr][cc + 3] = x.w;
        }
#pragma unroll
        for (int u = 0; u < 8; u++) {
            int fi = tid + u * 256;
            int rr = fi >> 5;
            int cc = fi & 31;
            Ws[rr][cc] = (cc < 16) ? Wmix[(k0 + rr) * 16 + cc]
                                   : Wgate[(k0 + rr) * 16 + (cc - 16)];
        }
        __syncthreads();
        for (int kk = 0; kk < 64; kk++) {
            float a = Ts[r][kk];
#pragma unroll
            for (int c = 0; c < 16; c++) acc[c] += a * Ws[kk][cg + c];
        }
        __syncthreads();
    }

    const int t = row0 + r;
#pragma unroll
    for (int c = 0; c < 16; c++) {
        float sg = 1.0f / (1.0f + expf(-acc[c]));
        int col = cg + c;
        if (col < 16) gmix[t * 16 + col] = sg;
        else          ggate[t * 16 + (col - 16)] = sg;
    }
}

// ---------------------------------------------------------------------------
// Sliding-window flash attention, fp16 HMMA:
// q = fp16 hi/lo (exact), k/v = fp16 single; P split in-register.
// CTA = (64-query tile, head, batch); 4 warps, warp = 16 rows x 64 keys.
// ---------------------------------------------------------------------------
#define APAD 72
#define ATT_SMEM (4*64*APAD*2)

__global__ void __launch_bounds__(128) attn_mma(
    const ush* __restrict__ qh, const ush* __restrict__ ql,
    const ush* __restrict__ kh, const ush* __restrict__ vh,
    const float* __restrict__ gate,
    ush* __restrict__ aoh, ush* __restrict__ aol)
{
    extern __shared__ ush smA[];
    ush* Qh = smA;
    ush* Ql = Qh + 64 * APAD;
    ush* Ks = Ql + 64 * APAD;
    ush* Vs = Ks + 64 * APAD;

    const int b = blockIdx.z, h = blockIdx.y, q0 = blockIdx.x * 64;
    const int tid = threadIdx.x, wid = tid >> 5, lane = tid & 31;
    const int wm = wid * 16;
    const size_t bbase = (size_t)b * Sn;
    const int hoff = h * Dn;

#pragma unroll
    for (int i = 0; i < 4; i++) {
        int e = tid + i * 128;
        int row = e >> 3, c = (e & 7) * 8;
        size_t g = (bbase + q0 + row) * (size_t)HDn + hoff + c;
        *(uint4*)(Qh + row * APAD + c) = *(const uint4*)(qh + g);
        *(uint4*)(Ql + row * APAD + c) = *(const uint4*)(ql + g);
    }
    __syncthreads();

    uint32_t qfh[4][4], qfl[4][4];
    {
        uint32_t qb = smem_u32(Qh), qbl = smem_u32(Ql);
        int arow = wm + (lane & 15);
        int ac0  = (lane >> 4) * 8;
#pragma unroll
        for (int ks = 0; ks < 4; ks++) {
            ldsm4(qfh[ks], qb  + (arow * APAD + ks * 16 + ac0) * 2);
            ldsm4(qfl[ks], qbl + (arow * APAD + ks * 16 + ac0) * 2);
        }
    }

    float mi0 = -1e30f, mi1 = -1e30f, li0 = 0.f, li1 = 0.f;
    float accO[8][4];
#pragma unroll
    for (int i = 0; i < 8; i++)
#pragma unroll
        for (int j = 0; j < 4; j++) accO[i][j] = 0.f;

    const int jt_lo = (q0 >= WIN) ? ((q0 - WIN) >> 6) : 0;
    const int jt_hi = q0 >> 6;
    const int gi0 = q0 + wm + (lane >> 2);
    const int gi1 = gi0 + 8;

    const uint32_t kb = smem_u32(Ks);
    const uint32_t vb = smem_u32(Vs);
    const int bn  = (lane & 7) | ((lane >> 1) & 8);
    const int bk8 = ((lane >> 3) & 1) * 8;
    const int vr0 = lane & 15;
    const int vc8 = (lane >> 4) * 8;

    for (int jt = jt_lo; jt <= jt_hi; jt++) {
        const int j0 = jt * 64;
#pragma unroll
        for (int i = 0; i < 4; i++) {
            int e = tid + i * 128;
            int row = e >> 3, c = (e & 7) * 8;
            size_t g = (bbase + j0 + row) * (size_t)HDn + hoff + c;
            *(uint4*)(Ks + row * APAD + c) = *(const uint4*)(kh + g);
            *(uint4*)(Vs + row * APAD + c) = *(const uint4*)(vh + g);
        }
        __syncthreads();

        float s[8][4];
#pragma unroll
        for (int i = 0; i < 8; i++)
#pragma unroll
            for (int j = 0; j < 4; j++) s[i][j] = 0.f;

        // S = (qh+ql) @ K^T : 4 fp16 MMAs per (ks, g2)
#pragma unroll
        for (int ks = 0; ks < 4; ks++) {
#pragma unroll
            for (int g2 = 0; g2 < 4; g2++) {
                uint32_t off = (uint32_t)(((g2 * 16 + bn) * APAD + ks * 16 + bk8) * 2);
                uint32_t rh[4];
                ldsm4(rh, kb + off);
                uint32_t bh0[2] = {rh[0], rh[1]}, bh1[2] = {rh[2], rh[3]};
                mma16816h(s[2*g2],   qfh[ks], bh0);
                mma16816h(s[2*g2],   qfl[ks], bh0);
                mma16816h(s[2*g2+1], qfh[ks], bh1);
                mma16816h(s[2*g2+1], qfl[ks], bh1);
            }
        }

        if (jt == jt_hi || (jt == jt_lo && q0 >= WIN)) {
#pragma unroll
            for (int nf = 0; nf < 8; nf++) {
                int cbase = j0 + nf * 8 + (lane & 3) * 2;
#pragma unroll
                for (int jj = 0; jj < 2; jj++) {
                    int gj = cbase + jj;
                    int d0 = gi0 - gj, d1 = gi1 - gj;
                    if (d0 < 0 || d0 > WIN) s[nf][jj]     = -1e30f;
                    if (d1 < 0 || d1 > WIN) s[nf][2 + jj] = -1e30f;
                }
            }
        }

        float mt0 = -1e30f, mt1 = -1e30f;
#pragma unroll
        for (int nf = 0; nf < 8; nf++) {
            mt0 = fmaxf(mt0, fmaxf(s[nf][0], s[nf][1]));
            mt1 = fmaxf(mt1, fmaxf(s[nf][2], s[nf][3]));
        }
        mt0 = fmaxf(mt0, __shfl_xor_sync(0xffffffffu, mt0, 1));
        mt0 = fmaxf(mt0, __shfl_xor_sync(0xffffffffu, mt0, 2));
        mt1 = fmaxf(mt1, __shfl_xor_sync(0xffffffffu, mt1, 1));
        mt1 = fmaxf(mt1, __shfl_xor_sync(0xffffffffu, mt1, 2));

        float mn0 = fmaxf(mi0, mt0), mn1 = fmaxf(mi1, mt1);
        float f0 = __expf(mi0 - mn0), f1 = __expf(mi1 - mn1);
        mi0 = mn0; mi1 = mn1;

        float su0 = 0.f, su1 = 0.f;
#pragma unroll
        for (int nf = 0; nf < 8; nf++) {
            s[nf][0] = __expf(s[nf][0] - mn0);
            s[nf][1] = __expf(s[nf][1] - mn0);
            s[nf][2] = __expf(s[nf][2] - mn1);
            s[nf][3] = __expf(s[nf][3] - mn1);
            su0 += s[nf][0] + s[nf][1];
            su1 += s[nf][2] + s[nf][3];
        }
        su0 += __shfl_xor_sync(0xffffffffu, su0, 1);
        su0 += __shfl_xor_sync(0xffffffffu, su0, 2);
        su1 += __shfl_xor_sync(0xffffffffu, su1, 1);
        su1 += __shfl_xor_sync(0xffffffffu, su1, 2);
        li0 = li0 * f0 + su0;
        li1 = li1 * f1 + su1;
#pragma unroll
        for (int nf = 0; nf < 8; nf++) {
            accO[nf][0] *= f0; accO[nf][1] *= f0;
            accO[nf][2] *= f1; accO[nf][3] *= f1;
        }

        // O += (Ph+Pl) @ V : 4 fp16 MMAs per (ks, g2)
#pragma unroll
        for (int ks = 0; ks < 4; ks++) {
            uint32_t ph[4], pl[4];
            const float* p0 = s[2 * ks];
            const float* p1 = s[2 * ks + 1];
            splitpairh(p0[0], p0[1], ph[0], pl[0]);
            splitpairh(p0[2], p0[3], ph[1], pl[1]);
            splitpairh(p1[0], p1[1], ph[2], pl[2]);
            splitpairh(p1[2], p1[3], ph[3], pl[3]);
#pragma unroll
            for (int g2 = 0; g2 < 4; g2++) {
                uint32_t off = (uint32_t)(((ks * 16 + vr0) * APAD + g2 * 16 + vc8) * 2);
                uint32_t rh[4];
                ldsm4t(rh, vb + off);
                uint32_t bh0[2] = {rh[0], rh[1]}, bh1[2] = {rh[2], rh[3]};
                mma16816h(accO[2*g2],   ph, bh0);
                mma16816h(accO[2*g2],   pl, bh0);
                mma16816h(accO[2*g2+1], ph, bh1);
                mma16816h(accO[2*g2+1], pl, bh1);
            }
        }
        __syncthreads();
    }

    float g0 = gate[(bbase + gi0) * Hn + h];
    float g1 = gate[(bbase + gi1) * Hn + h];
    float sc0 = g0 / li0, sc1 = g1 / li1;
#pragma unroll
    for (int nf = 0; nf < 8; nf++) {
        int col = hoff + nf * 8 + (lane & 3) * 2;
        size_t i0 = (bbase + gi0) * (size_t)HDn + col;
        size_t i1 = (bbase + gi1) * (size_t)HDn + col;
        uint32_t hp, lp;
        splitpairh(accO[nf][0] * sc0, accO[nf][1] * sc0, hp, lp);
        *(uint32_t*)(aoh + i0) = hp;
        *(uint32_t*)(aol + i0) = lp;
        splitpairh(accO[nf][2] * sc1, accO[nf][3] * sc1, hp, lp);
        *(uint32_t*)(aoh + i1) = hp;
        *(uint32_t*)(aol + i1) = lp;
    }
}

// ---------------------------------------------------------------------------
extern "C" void kernel_launch(void* const* d_in, const int* in_sizes, int n_in,
                              void* d_out, int out_size)
{
    const float* tokens = (const float*)d_in[0];
    const float* vres   = (const float*)d_in[1];
    const float* Wq     = (const float*)d_in[2];
    const float* Wkv    = (const float*)d_in[3];
    const float* Wout   = (const float*)d_in[4];
    const float* Wgate  = (const float*)d_in[5];
    const float* Wmix   = (const float*)d_in[6];
    float* out = (float*)d_out;

    float *pmix, *pgate;
    ush *tkh, *tkl, *aoh, *aol, *wah, *woh;
    ush *qsh, *qsl, *ksp, *vsp;
    cudaGetSymbolAddress((void**)&pmix, g_mix);
    cudaGetSymbolAddress((void**)&pgate,g_gate);
    cudaGetSymbolAddress((void**)&tkh,  g_tokh);
    cudaGetSymbolAddress((void**)&tkl,  g_tokl);
    cudaGetSymbolAddress((void**)&aoh,  g_aoh);
    cudaGetSymbolAddress((void**)&aol,  g_aol);
    cudaGetSymbolAddress((void**)&wah,  g_wallh);
    cudaGetSymbolAddress((void**)&woh,  g_woh);
    cudaGetSymbolAddress((void**)&qsh,  g_qsh);
    cudaGetSymbolAddress((void**)&qsl,  g_qsl);
    cudaGetSymbolAddress((void**)&ksp,  g_ks);
    cudaGetSymbolAddress((void**)&vsp,  g_vs);

    cudaFuncSetAttribute(gemm_mma, cudaFuncAttributeMaxDynamicSharedMemorySize, GEMM_SMEM);
    cudaFuncSetAttribute(attn_mma, cudaFuncAttributeMaxDynamicSharedMemorySize, ATT_SMEM);

    // 1. splits: tokens (fp16 hi/lo); weights single fp16 transposed
    convA<<<(Tn * DIMn / 4 + 255) / 256, 256>>>(tokens, tkh, tkl, Tn * DIMn / 4);
    convW<<<dim3(1024 / 32, 1024 / 32), dim3(32, 8)>>>(Wq,  wah,               1024, 1024);
    convW<<<dim3(2048 / 32, 1024 / 32), dim3(32, 8)>>>(Wkv, wah + 1024 * 1024, 1024, 2048);
    convW<<<dim3(1024 / 32, 1024 / 32), dim3(32, 8)>>>(Wout, woh, 1024, 1024);

    // 2. mix / gate logits + sigmoid
    mixgate<<<64, 256>>>(tokens, Wmix, Wgate, pmix, pgate);

    // 3. merged QKV projection (fp16 2-term) with fused rope / v-mix epilogue
    gemm_mma<<<dim3(24, 64), 256, GEMM_SMEM>>>(
        tkh, tkl, wah, nullptr,
        qsh, qsl, ksp, vsp, vres, pmix, 1);

    // 4. windowed attention (fp16) + gate, writes fp16 ao splits
    attn_mma<<<dim3(Sn / 64, Hn, Bn), 128, ATT_SMEM>>>(
        qsh, qsl, ksp, vsp, pgate, aoh, aol);

    // 5. output projection (fp16 2-term) into d_out
    gemm_mma<<<dim3(8, 64), 256, GEMM_SMEM>>>(
        aoh, aol, woh, out,
        nullptr, nullptr, nullptr, nullptr, nullptr, nullptr, 0);
}

// round 10
// speedup vs baseline: 1.8422x; 1.2253x over previous
#include <cuda_runtime.h>
#include <cuda_bf16.h>
#include <cuda_fp16.h>
#include <math.h>
#include <stdint.h>

// Problem constants
#define Bn 4
#define Sn 2048
#define DIMn 1024
#define Hn 16
#define Dn 64
#define Tn (Bn*Sn)      // 8192 tokens
#define HDn 1024
#define WIN 512

typedef unsigned short ush;

// ---------------------------------------------------------------------------
// Scratch (device globals)
// ---------------------------------------------------------------------------
__device__ float g_mix[Tn*Hn];
__device__ float g_gate[Tn*Hn];

__device__ ush g_tok[(size_t)Tn*DIMn];    // fp16 single (tokens)
__device__ ush g_aoh[(size_t)Tn*HDn];     // fp16 hi (attention output)
__device__ ush g_aol[(size_t)Tn*HDn];     // fp16 lo
__device__ ush g_wallh[3072*1024];        // fp16 single: [Wq|Wk|Wv]^T [N=3072,K=1024]
__device__ ush g_woh[1024*1024];          // fp16 single: Wout^T
// attention operands: q fp16 hi/lo, k/v fp16 single
__device__ ush g_qsh[(size_t)Tn*HDn];
__device__ ush g_qsl[(size_t)Tn*HDn];
__device__ ush g_ks[(size_t)Tn*HDn];
__device__ ush g_vs[(size_t)Tn*HDn];

// ---------------------------------------------------------------------------
// Helpers (base sm_103 target — mma.sync / ldmatrix / cp.async, NO tcgen05)
// ---------------------------------------------------------------------------
__device__ __forceinline__ uint32_t smem_u32(const void* p) {
    uint32_t a;
    asm("{ .reg .u64 t; cvta.to.shared.u64 t, %1; cvt.u32.u64 %0, t; }" : "=r"(a) : "l"(p));
    return a;
}
__device__ __forceinline__ void ldsm4(uint32_t* r, uint32_t addr) {
    asm volatile("ldmatrix.sync.aligned.m8n8.x4.shared.b16 {%0,%1,%2,%3}, [%4];"
                 : "=r"(r[0]), "=r"(r[1]), "=r"(r[2]), "=r"(r[3]) : "r"(addr));
}
__device__ __forceinline__ void ldsm4t(uint32_t* r, uint32_t addr) {
    asm volatile("ldmatrix.sync.aligned.m8n8.x4.trans.shared.b16 {%0,%1,%2,%3}, [%4];"
                 : "=r"(r[0]), "=r"(r[1]), "=r"(r[2]), "=r"(r[3]) : "r"(addr));
}
__device__ __forceinline__ void mma16816h(float* d, const uint32_t* a, const uint32_t* b) {
    asm volatile("mma.sync.aligned.m16n8k16.row.col.f32.f16.f16.f32 "
                 "{%0,%1,%2,%3},{%4,%5,%6,%7},{%8,%9},{%0,%1,%2,%3};"
                 : "+f"(d[0]), "+f"(d[1]), "+f"(d[2]), "+f"(d[3])
                 : "r"(a[0]), "r"(a[1]), "r"(a[2]), "r"(a[3]),
                   "r"(b[0]), "r"(b[1]));
}
__device__ __forceinline__ void cp16(uint32_t smem, const void* g) {
    asm volatile("cp.async.cg.shared.global [%0], [%1], 16;" :: "r"(smem), "l"(g));
}
__device__ __forceinline__ uint32_t packh(float y0, float y1) {
    __half2 h = __floats2half2_rn(y0, y1);
    return *reinterpret_cast<uint32_t*>(&h);
}
__device__ __forceinline__ void splitpairh(float y0, float y1, uint32_t& hp, uint32_t& lp) {
    __half2 h = __floats2half2_rn(y0, y1);
    hp = *reinterpret_cast<uint32_t*>(&h);
    __half2 l = __floats2half2_rn(y0 - __low2float(h), y1 - __high2float(h));
    lp = *reinterpret_cast<uint32_t*>(&l);
}

// ---------------------------------------------------------------------------
// fp32 -> fp16 single cast (elementwise)
// ---------------------------------------------------------------------------
__global__ void conv1(const float* __restrict__ x, ush* __restrict__ h, int n4)
{
    int i = blockIdx.x * blockDim.x + threadIdx.x;
    if (i >= n4) return;
    float4 v = ((const float4*)x)[i];
    uint32_t p0 = packh(v.x, v.y), p1 = packh(v.z, v.w);
    ((uint2*)h)[i] = make_uint2(p0, p1);
}

// W [K,N] fp32 -> W^T [N,K] fp16 single (transpose via smem)
__global__ void convW(const float* __restrict__ W, ush* __restrict__ Th, int K, int N)
{
    __shared__ float t[32][33];
    int n0 = blockIdx.x * 32, k0 = blockIdx.y * 32;
    int tx = threadIdx.x, ty = threadIdx.y;   // blockDim (32, 8)
#pragma unroll
    for (int r = 0; r < 4; r++)
        t[ty + 8 * r][tx] = W[(size_t)(k0 + ty + 8 * r) * N + n0 + tx];
    __syncthreads();
#pragma unroll
    for (int r = 0; r < 4; r++) {
        float v = t[tx][ty + 8 * r];
        __half hb = __float2half_rn(v);
        Th[(size_t)(n0 + ty + 8 * r) * K + k0 + tx] = *reinterpret_cast<ush*>(&hb);
    }
}

// ---------------------------------------------------------------------------
// fp16 GEMM, TERMS = A-operand term count (1: A single; 2: A = Ah+Al exact).
// CTA 128x128, 256 thr, 8 warps (4m x 2n), warp 32x64, K-chunk 32, dbl-buffer.
// mode 0: fp32 C store. mode 1: fused QKV epilogue:
//   seg0 rope+scale -> q fp16 hi/lo; seg1 rope -> k single; seg2 v-mix -> v single.
// ---------------------------------------------------------------------------
#define PADE 40
#define KIND_ELEMS (128*PADE)            // 5120 ush = 10KB
#define GSMEM(T) (2*((T)+1)*KIND_ELEMS*2)

template<int TERMS>
__global__ void __launch_bounds__(256, 2) gemm_mma(
    const ush* __restrict__ Ah, const ush* __restrict__ Al,
    const ush* __restrict__ Bh,
    float* __restrict__ C,
    ush* __restrict__ qh, ush* __restrict__ ql,
    ush* __restrict__ ks, ush* __restrict__ vs,
    const float* __restrict__ vres, const float* __restrict__ mix,
    int mode)
{
    constexpr int NKIND = TERMS + 1;
    constexpr int STAGE_ELEMS = NKIND * KIND_ELEMS;

    extern __shared__ ush sh[];
    const int tid  = threadIdx.x;
    const int wid  = tid >> 5, lane = tid & 31;
    const int brow = blockIdx.y * 128, bcol = blockIdx.x * 128;
    const int wm   = (wid & 3) * 32;
    const int wn   = (wid >> 2) * 64;
    const int K    = 1024;

    const uint32_t sbase = smem_u32(sh);

    float acc[2][8][4];
#pragma unroll
    for (int i = 0; i < 2; i++)
#pragma unroll
        for (int j = 0; j < 8; j++)
#pragma unroll
            for (int k = 0; k < 4; k++) acc[i][j][k] = 0.f;

    const ush* srcs[NKIND];
    int rbase[NKIND];
    srcs[0] = Ah;        rbase[0] = brow;
    if (TERMS == 2) { srcs[1] = Al; rbase[1] = brow; }
    srcs[TERMS] = Bh;    rbase[TERMS] = bcol;

    auto cp_chunk = [&](int k0, int buf) {
#pragma unroll
        for (int kind = 0; kind < NKIND; kind++) {
#pragma unroll
            for (int half = 0; half < 2; half++) {
                int e = tid + half * 256;
                int row = e >> 2, ce = (e & 3) * 8;
                const ush* g = srcs[kind] + (size_t)(rbase[kind] + row) * K + k0 + ce;
                uint32_t d = sbase + (uint32_t)(buf * STAGE_ELEMS + kind * KIND_ELEMS +
                                                row * PADE + ce) * 2;
                cp16(d, g);
            }
        }
        asm volatile("cp.async.commit_group;" ::: "memory");
    };

    cp_chunk(0, 0);

    for (int c = 0; c < 32; c++) {
        int buf = c & 1;
        if (c < 31) {
            cp_chunk((c + 1) * 32, buf ^ 1);
            asm volatile("cp.async.wait_group 1;" ::: "memory");
        } else {
            asm volatile("cp.async.wait_group 0;" ::: "memory");
        }
        __syncthreads();

        uint32_t abase = sbase + (uint32_t)buf * STAGE_ELEMS * 2;

#pragma unroll
        for (int ksub = 0; ksub < 2; ksub++) {
            uint32_t a[TERMS][2][4];
            {
                int arow = wm + (lane & 15);
                int acol = ksub * 16 + (lane >> 4) * 8;
#pragma unroll
                for (int sp = 0; sp < TERMS; sp++)
#pragma unroll
                    for (int ms = 0; ms < 2; ms++)
                        ldsm4(a[sp][ms], abase + (uint32_t)(sp * KIND_ELEMS +
                              (arow + ms * 16) * PADE + acol) * 2);
            }
            uint32_t b[8][2];
            {
                int bn = (lane & 7) | ((lane >> 1) & 8);
                int bk = ksub * 16 + ((lane >> 3) & 1) * 8;
#pragma unroll
                for (int g = 0; g < 4; g++) {
                    uint32_t r[4];
                    ldsm4(r, abase + (uint32_t)(TERMS * KIND_ELEMS +
                          (wn + g * 16 + bn) * PADE + bk) * 2);
                    b[2 * g][0]     = r[0]; b[2 * g][1]     = r[1];
                    b[2 * g + 1][0] = r[2]; b[2 * g + 1][1] = r[3];
                }
            }
#pragma unroll
            for (int ms = 0; ms < 2; ms++)
#pragma unroll
                for (int nf = 0; nf < 8; nf++) {
#pragma unroll
                    for (int sp = 0; sp < TERMS; sp++)
                        mma16816h(acc[ms][nf], a[sp][ms], b[nf]);
                }
        }
        __syncthreads();
    }

    if (mode == 0) {
#pragma unroll
        for (int ms = 0; ms < 2; ms++) {
            int r0 = brow + wm + ms * 16 + (lane >> 2);
#pragma unroll
            for (int nf = 0; nf < 8; nf++) {
                int cc = bcol + wn + nf * 8 + 2 * (lane & 3);
                *(float2*)(C + (size_t)r0 * 1024 + cc)       = make_float2(acc[ms][nf][0], acc[ms][nf][1]);
                *(float2*)(C + (size_t)(r0 + 8) * 1024 + cc) = make_float2(acc[ms][nf][2], acc[ms][nf][3]);
            }
        }
        return;
    }

    // fused QKV epilogue
    const int seg  = bcol >> 10;          // 0=q, 1=k, 2=v
    const int colb = (bcol & 1023) + wn + 2 * (lane & 3);
    const float qscale = (seg == 0) ? 0.125f : 1.0f;
    const float L2F = 13.2877123795494f / 32.0f;   // log2(10000)/32

#pragma unroll
    for (int ms = 0; ms < 2; ms++) {
        int r0 = brow + wm + ms * 16 + (lane >> 2);
#pragma unroll
        for (int half = 0; half < 2; half++) {
            int row = r0 + half * 8;
            int s = row & (Sn - 1);
            int bb = row >> 11;
#pragma unroll
            for (int nf = 0; nf < 8; nf++) {
                float x0 = acc[ms][nf][half * 2 + 0];
                float x1 = acc[ms][nf][half * 2 + 1];
                int colc = colb + nf * 8;
                size_t o = (size_t)row * 1024 + colc;
                if (seg < 2) {
                    int i = (colc & 63) >> 1;
                    float inv = exp2f(-(float)i * L2F);
                    float ang = (float)s * inv;
                    float sn, cs;
                    sincosf(ang, &sn, &cs);
                    float y0 = (x0 * cs - x1 * sn) * qscale;
                    float y1 = (x1 * cs + x0 * sn) * qscale;
                    if (seg == 0) {
                        uint32_t hp, lp;
                        splitpairh(y0, y1, hp, lp);
                        *(uint32_t*)(qh + o) = hp;
                        *(uint32_t*)(ql + o) = lp;
                    } else {
                        *(uint32_t*)(ks + o) = packh(y0, y1);
                    }
                } else {
                    int hh = (colc & 1023) >> 6;
                    int d  = colc & 63;
                    float m = mix[row * Hn + hh];
                    const float* rp = vres + (((size_t)bb * Hn + hh) * Sn + s) * Dn + d;
                    float2 rr = *(const float2*)rp;
                    float y0 = x0 + (rr.x - x0) * m;
                    float y1 = x1 + (rr.y - x1) * m;
                    *(uint32_t*)(vs + o) = packh(y0, y1);
                }
            }
        }
    }
}

// ---------------------------------------------------------------------------
// mix/gate: (8192 x 1024) @ [Wmix | Wgate] (1024 x 32), sigmoid epilogue.
// ---------------------------------------------------------------------------
__global__ void __launch_bounds__(256) mixgate(
    const float* __restrict__ tokens, const float* __restrict__ Wmix,
    const float* __restrict__ Wgate, float* __restrict__ gmix,
    float* __restrict__ ggate)
{
    __shared__ float Ts[128][65];
    __shared__ float Ws[64][32];

    const int tid  = threadIdx.x;
    const int row0 = blockIdx.x * 128;
    const int r  = tid >> 1;
    const int cg = (tid & 1) << 4;

    float acc[16];
#pragma unroll
    for (int c = 0; c < 16; c++) acc[c] = 0.f;

    for (int k0 = 0; k0 < 1024; k0 += 64) {
#pragma unroll
        for (int u = 0; u < 8; u++) {
            int fi = tid + u * 256;
            int rr = fi >> 4;
            int cc = (fi & 15) << 2;
            float4 x = *(const float4*)(tokens + (size_t)(row0 + rr) * 1024 + k0 + cc);
            Ts[rr][cc] = x.x; Ts[rr][cc + 1] = x.y; Ts[rr][cc + 2] = x.z; Ts[rr][cc + 3] = x.w;
        }
#pragma unroll
        for (int u = 0; u < 8; u++) {
            int fi = tid + u * 256;
            int rr = fi >> 5;
            int cc = fi & 31;
            Ws[rr][cc] = (cc < 16) ? Wmix[(k0 + rr) * 16 + cc]
                                   : Wgate[(k0 + rr) * 16 + (cc - 16)];
        }
        __syncthreads();
        for (int kk = 0; kk < 64; kk++) {
            float a = Ts[r][kk];
#pragma unroll
            for (int c = 0; c < 16; c++) acc[c] += a * Ws[kk][cg + c];
        }
        __syncthreads();
    }

    const int t = row0 + r;
#pragma unroll
    for (int c = 0; c < 16; c++) {
        float sg = 1.0f / (1.0f + expf(-acc[c]));
        int col = cg + c;
        if (col < 16) gmix[t * 16 + col] = sg;
        else          ggate[t * 16 + (col - 16)] = sg;
    }
}

// ---------------------------------------------------------------------------
// Sliding-window flash attention, fp16 HMMA:
// q = fp16 hi/lo (exact), k/v = fp16 single; P split in-register.
// CTA = (64-query tile, head, batch); 4 warps, warp = 16 rows x 64 keys.
// ---------------------------------------------------------------------------
#define APAD 72
#define ATT_SMEM (4*64*APAD*2)

__global__ void __launch_bounds__(128) attn_mma(
    const ush* __restrict__ qh, const ush* __restrict__ ql,
    const ush* __restrict__ kh, const ush* __restrict__ vh,
    const float* __restrict__ gate,
    ush* __restrict__ aoh, ush* __restrict__ aol)
{
    extern __shared__ ush smA[];
    ush* Qh = smA;
    ush* Ql = Qh + 64 * APAD;
    ush* Ks = Ql + 64 * APAD;
    ush* Vs = Ks + 64 * APAD;

    const int b = blockIdx.z, h = blockIdx.y, q0 = blockIdx.x * 64;
    const int tid = threadIdx.x, wid = tid >> 5, lane = tid & 31;
    const int wm = wid * 16;
    const size_t bbase = (size_t)b * Sn;
    const int hoff = h * Dn;

#pragma unroll
    for (int i = 0; i < 4; i++) {
        int e = tid + i * 128;
        int row = e >> 3, c = (e & 7) * 8;
        size_t g = (bbase + q0 + row) * (size_t)HDn + hoff + c;
        *(uint4*)(Qh + row * APAD + c) = *(const uint4*)(qh + g);
        *(uint4*)(Ql + row * APAD + c) = *(const uint4*)(ql + g);
    }
    __syncthreads();

    uint32_t qfh[4][4], qfl[4][4];
    {
        uint32_t qb = smem_u32(Qh), qbl = smem_u32(Ql);
        int arow = wm + (lane & 15);
        int ac0  = (lane >> 4) * 8;
#pragma unroll
        for (int ks = 0; ks < 4; ks++) {
            ldsm4(qfh[ks], qb  + (arow * APAD + ks * 16 + ac0) * 2);
            ldsm4(qfl[ks], qbl + (arow * APAD + ks * 16 + ac0) * 2);
        }
    }

    float mi0 = -1e30f, mi1 = -1e30f, li0 = 0.f, li1 = 0.f;
    float accO[8][4];
#pragma unroll
    for (int i = 0; i < 8; i++)
#pragma unroll
        for (int j = 0; j < 4; j++) accO[i][j] = 0.f;

    const int jt_lo = (q0 >= WIN) ? ((q0 - WIN) >> 6) : 0;
    const int jt_hi = q0 >> 6;
    const int gi0 = q0 + wm + (lane >> 2);
    const int gi1 = gi0 + 8;

    const uint32_t kb = smem_u32(Ks);
    const uint32_t vb = smem_u32(Vs);
    const int bn  = (lane & 7) | ((lane >> 1) & 8);
    const int bk8 = ((lane >> 3) & 1) * 8;
    const int vr0 = lane & 15;
    const int vc8 = (lane >> 4) * 8;

    for (int jt = jt_lo; jt <= jt_hi; jt++) {
        const int j0 = jt * 64;
#pragma unroll
        for (int i = 0; i < 4; i++) {
            int e = tid + i * 128;
            int row = e >> 3, c = (e & 7) * 8;
            size_t g = (bbase + j0 + row) * (size_t)HDn + hoff + c;
            *(uint4*)(Ks + row * APAD + c) = *(const uint4*)(kh + g);
            *(uint4*)(Vs + row * APAD + c) = *(const uint4*)(vh + g);
        }
        __syncthreads();

        float s[8][4];
#pragma unroll
        for (int i = 0; i < 8; i++)
#pragma unroll
            for (int j = 0; j < 4; j++) s[i][j] = 0.f;

        // S = (qh+ql) @ K^T
#pragma unroll
        for (int ks = 0; ks < 4; ks++) {
#pragma unroll
            for (int g2 = 0; g2 < 4; g2++) {
                uint32_t off = (uint32_t)(((g2 * 16 + bn) * APAD + ks * 16 + bk8) * 2);
                uint32_t rh[4];
                ldsm4(rh, kb + off);
                uint32_t bh0[2] = {rh[0], rh[1]}, bh1[2] = {rh[2], rh[3]};
                mma16816h(s[2*g2],   qfh[ks], bh0);
                mma16816h(s[2*g2],   qfl[ks], bh0);
                mma16816h(s[2*g2+1], qfh[ks], bh1);
                mma16816h(s[2*g2+1], qfl[ks], bh1);
            }
        }

        if (jt == jt_hi || (jt == jt_lo && q0 >= WIN)) {
#pragma unroll
            for (int nf = 0; nf < 8; nf++) {
                int cbase = j0 + nf * 8 + (lane & 3) * 2;
#pragma unroll
                for (int jj = 0; jj < 2; jj++) {
                    int gj = cbase + jj;
                    int d0 = gi0 - gj, d1 = gi1 - gj;
                    if (d0 < 0 || d0 > WIN) s[nf][jj]     = -1e30f;
                    if (d1 < 0 || d1 > WIN) s[nf][2 + jj] = -1e30f;
                }
            }
        }

        float mt0 = -1e30f, mt1 = -1e30f;
#pragma unroll
        for (int nf = 0; nf < 8; nf++) {
            mt0 = fmaxf(mt0, fmaxf(s[nf][0], s[nf][1]));
            mt1 = fmaxf(mt1, fmaxf(s[nf][2], s[nf][3]));
        }
        mt0 = fmaxf(mt0, __shfl_xor_sync(0xffffffffu, mt0, 1));
        mt0 = fmaxf(mt0, __shfl_xor_sync(0xffffffffu, mt0, 2));
        mt1 = fmaxf(mt1, __shfl_xor_sync(0xffffffffu, mt1, 1));
        mt1 = fmaxf(mt1, __shfl_xor_sync(0xffffffffu, mt1, 2));

        float mn0 = fmaxf(mi0, mt0), mn1 = fmaxf(mi1, mt1);
        float f0 = __expf(mi0 - mn0), f1 = __expf(mi1 - mn1);
        mi0 = mn0; mi1 = mn1;

        float su0 = 0.f, su1 = 0.f;
#pragma unroll
        for (int nf = 0; nf < 8; nf++) {
            s[nf][0] = __expf(s[nf][0] - mn0);
            s[nf][1] = __expf(s[nf][1] - mn0);
            s[nf][2] = __expf(s[nf][2] - mn1);
            s[nf][3] = __expf(s[nf][3] - mn1);
            su0 += s[nf][0] + s[nf][1];
            su1 += s[nf][2] + s[nf][3];
        }
        su0 += __shfl_xor_sync(0xffffffffu, su0, 1);
        su0 += __shfl_xor_sync(0xffffffffu, su0, 2);
        su1 += __shfl_xor_sync(0xffffffffu, su1, 1);
        su1 += __shfl_xor_sync(0xffffffffu, su1, 2);
        li0 = li0 * f0 + su0;
        li1 = li1 * f1 + su1;
#pragma unroll
        for (int nf = 0; nf < 8; nf++) {
            accO[nf][0] *= f0; accO[nf][1] *= f0;
            accO[nf][2] *= f1; accO[nf][3] *= f1;
        }

        // O += (Ph+Pl) @ V
#pragma unroll
        for (int ks = 0; ks < 4; ks++) {
            uint32_t ph[4], pl[4];
            const float* p0 = s[2 * ks];
            const float* p1 = s[2 * ks + 1];
            splitpairh(p0[0], p0[1], ph[0], pl[0]);
            splitpairh(p0[2], p0[3], ph[1], pl[1]);
            splitpairh(p1[0], p1[1], ph[2], pl[2]);
            splitpairh(p1[2], p1[3], ph[3], pl[3]);
#pragma unroll
            for (int g2 = 0; g2 < 4; g2++) {
                uint32_t off = (uint32_t)(((ks * 16 + vr0) * APAD + g2 * 16 + vc8) * 2);
                uint32_t rh[4];
                ldsm4t(rh, vb + off);
                uint32_t bh0[2] = {rh[0], rh[1]}, bh1[2] = {rh[2], rh[3]};
                mma16816h(accO[2*g2],   ph, bh0);
                mma16816h(accO[2*g2],   pl, bh0);
                mma16816h(accO[2*g2+1], ph, bh1);
                mma16816h(accO[2*g2+1], pl, bh1);
            }
        }
        __syncthreads();
    }

    float g0 = gate[(bbase + gi0) * Hn + h];
    float g1 = gate[(bbase + gi1) * Hn + h];
    float sc0 = g0 / li0, sc1 = g1 / li1;
#pragma unroll
    for (int nf = 0; nf < 8; nf++) {
        int col = hoff + nf * 8 + (lane & 3) * 2;
        size_t i0 = (bbase + gi0) * (size_t)HDn + col;
        size_t i1 = (bbase + gi1) * (size_t)HDn + col;
        uint32_t hp, lp;
        splitpairh(accO[nf][0] * sc0, accO[nf][1] * sc0, hp, lp);
        *(uint32_t*)(aoh + i0) = hp;
        *(uint32_t*)(aol + i0) = lp;
        splitpairh(accO[nf][2] * sc1, accO[nf][3] * sc1, hp, lp);
        *(uint32_t*)(aoh + i1) = hp;
        *(uint32_t*)(aol + i1) = lp;
    }
}

// ---------------------------------------------------------------------------
extern "C" void kernel_launch(void* const* d_in, const int* in_sizes, int n_in,
                              void* d_out, int out_size)
{
    const float* tokens = (const float*)d_in[0];
    const float* vres   = (const float*)d_in[1];
    const float* Wq     = (const float*)d_in[2];
    const float* Wkv    = (const float*)d_in[3];
    const float* Wout   = (const float*)d_in[4];
    const float* Wgate  = (const float*)d_in[5];
    const float* Wmix   = (const float*)d_in[6];
    float* out = (float*)d_out;

    float *pmix, *pgate;
    ush *tk, *aoh, *aol, *wah, *woh;
    ush *qsh, *qsl, *ksp, *vsp;
    cudaGetSymbolAddress((void**)&pmix, g_mix);
    cudaGetSymbolAddress((void**)&pgate,g_gate);
    cudaGetSymbolAddress((void**)&tk,   g_tok);
    cudaGetSymbolAddress((void**)&aoh,  g_aoh);
    cudaGetSymbolAddress((void**)&aol,  g_aol);
    cudaGetSymbolAddress((void**)&wah,  g_wallh);
    cudaGetSymbolAddress((void**)&woh,  g_woh);
    cudaGetSymbolAddress((void**)&qsh,  g_qsh);
    cudaGetSymbolAddress((void**)&qsl,  g_qsl);
    cudaGetSymbolAddress((void**)&ksp,  g_ks);
    cudaGetSymbolAddress((void**)&vsp,  g_vs);

    cudaFuncSetAttribute(gemm_mma<1>, cudaFuncAttributeMaxDynamicSharedMemorySize, GSMEM(1));
    cudaFuncSetAttribute(gemm_mma<2>, cudaFuncAttributeMaxDynamicSharedMemorySize, GSMEM(2));
    cudaFuncSetAttribute(attn_mma, cudaFuncAttributeMaxDynamicSharedMemorySize, ATT_SMEM);

    // 1. casts: tokens fp16 single; weights fp16 single transposed
    conv1<<<(Tn * DIMn / 4 + 255) / 256, 256>>>(tokens, tk, Tn * DIMn / 4);
    convW<<<dim3(1024 / 32, 1024 / 32), dim3(32, 8)>>>(Wq,  wah,               1024, 1024);
    convW<<<dim3(2048 / 32, 1024 / 32), dim3(32, 8)>>>(Wkv, wah + 1024 * 1024, 1024, 2048);
    convW<<<dim3(1024 / 32, 1024 / 32), dim3(32, 8)>>>(Wout, woh, 1024, 1024);

    // 2. mix / gate logits + sigmoid
    mixgate<<<64, 256>>>(tokens, Wmix, Wgate, pmix, pgate);

    // 3. merged QKV projection (fp16 1-term) with fused rope / v-mix epilogue
    gemm_mma<1><<<dim3(24, 64), 256, GSMEM(1)>>>(
        tk, nullptr, wah, nullptr,
        qsh, qsl, ksp, vsp, vres, pmix, 1);

    // 4. windowed attention (fp16) + gate, writes fp16 ao splits
    attn_mma<<<dim3(Sn / 64, Hn, Bn), 128, ATT_SMEM>>>(
        qsh, qsl, ksp, vsp, pgate, aoh, aol);

    // 5. output projection (fp16 2-term, ao exact) into d_out
    gemm_mma<2><<<dim3(8, 64), 256, GSMEM(2)>>>(
        aoh, aol, woh, out,
        nullptr, nullptr, nullptr, nullptr, nullptr, nullptr, 0);
}

// round 11
// speedup vs baseline: 2.2264x; 1.2085x over previous
#include <cuda_runtime.h>
#include <cuda_fp16.h>
#include <math.h>
#include <stdint.h>

// Problem constants
#define Bn 4
#define Sn 2048
#define DIMn 1024
#define Hn 16
#define Dn 64
#define Tn (Bn*Sn)      // 8192 tokens
#define HDn 1024
#define WIN 512

typedef unsigned short ush;

// ---------------------------------------------------------------------------
// Scratch (device globals)
// ---------------------------------------------------------------------------
__device__ float g_mix[Tn*Hn];
__device__ float g_gate[Tn*Hn];

__device__ ush g_tok[(size_t)Tn*DIMn];    // fp16 tokens
__device__ ush g_ao[(size_t)Tn*HDn];      // fp16 attention output
__device__ ush g_wallh[3072*1024];        // fp16: [Wq|Wk|Wv]^T [N=3072,K=1024]
__device__ ush g_woh[1024*1024];          // fp16: Wout^T
__device__ ush g_qs[(size_t)Tn*HDn];      // fp16 q (post-rope, scaled)
__device__ ush g_ks[(size_t)Tn*HDn];      // fp16 k (post-rope)
__device__ ush g_vs[(size_t)Tn*HDn];      // fp16 v (post-mix)

// ---------------------------------------------------------------------------
// Helpers (base sm_103 target — mma.sync / ldmatrix / cp.async, NO tcgen05)
// ---------------------------------------------------------------------------
__device__ __forceinline__ uint32_t smem_u32(const void* p) {
    uint32_t a;
    asm("{ .reg .u64 t; cvta.to.shared.u64 t, %1; cvt.u32.u64 %0, t; }" : "=r"(a) : "l"(p));
    return a;
}
__device__ __forceinline__ void ldsm4(uint32_t* r, uint32_t addr) {
    asm volatile("ldmatrix.sync.aligned.m8n8.x4.shared.b16 {%0,%1,%2,%3}, [%4];"
                 : "=r"(r[0]), "=r"(r[1]), "=r"(r[2]), "=r"(r[3]) : "r"(addr));
}
__device__ __forceinline__ void ldsm4t(uint32_t* r, uint32_t addr) {
    asm volatile("ldmatrix.sync.aligned.m8n8.x4.trans.shared.b16 {%0,%1,%2,%3}, [%4];"
                 : "=r"(r[0]), "=r"(r[1]), "=r"(r[2]), "=r"(r[3]) : "r"(addr));
}
__device__ __forceinline__ void mma16816h(float* d, const uint32_t* a, const uint32_t* b) {
    asm volatile("mma.sync.aligned.m16n8k16.row.col.f32.f16.f16.f32 "
                 "{%0,%1,%2,%3},{%4,%5,%6,%7},{%8,%9},{%0,%1,%2,%3};"
                 : "+f"(d[0]), "+f"(d[1]), "+f"(d[2]), "+f"(d[3])
                 : "r"(a[0]), "r"(a[1]), "r"(a[2]), "r"(a[3]),
                   "r"(b[0]), "r"(b[1]));
}
__device__ __forceinline__ void cp16(uint32_t smem, const void* g) {
    asm volatile("cp.async.cg.shared.global [%0], [%1], 16;" :: "r"(smem), "l"(g));
}
__device__ __forceinline__ uint32_t packh(float y0, float y1) {
    __half2 h = __floats2half2_rn(y0, y1);
    return *reinterpret_cast<uint32_t*>(&h);
}

// ---------------------------------------------------------------------------
// fp32 -> fp16 cast (elementwise)
// ---------------------------------------------------------------------------
__global__ void conv1(const float* __restrict__ x, ush* __restrict__ h, int n4)
{
    int i = blockIdx.x * blockDim.x + threadIdx.x;
    if (i >= n4) return;
    float4 v = ((const float4*)x)[i];
    ((uint2*)h)[i] = make_uint2(packh(v.x, v.y), packh(v.z, v.w));
}

// W [K,N] fp32 -> W^T [N,K] fp16 (transpose via smem)
__global__ void convW(const float* __restrict__ W, ush* __restrict__ Th, int K, int N)
{
    __shared__ float t[32][33];
    int n0 = blockIdx.x * 32, k0 = blockIdx.y * 32;
    int tx = threadIdx.x, ty = threadIdx.y;   // blockDim (32, 8)
#pragma unroll
    for (int r = 0; r < 4; r++)
        t[ty + 8 * r][tx] = W[(size_t)(k0 + ty + 8 * r) * N + n0 + tx];
    __syncthreads();
#pragma unroll
    for (int r = 0; r < 4; r++) {
        float v = t[tx][ty + 8 * r];
        __half hb = __float2half_rn(v);
        Th[(size_t)(n0 + ty + 8 * r) * K + k0 + tx] = *reinterpret_cast<ush*>(&hb);
    }
}

// ---------------------------------------------------------------------------
// fp16 GEMM: C = A @ B^T. CTA 128x128, 256 thr, 8 warps (4m x 2n),
// warp 32x64, K-chunk 32, double-buffered cp.async.
// mode 0: fp32 C store. mode 1: fused QKV epilogue (rope / v-mix -> fp16).
// ---------------------------------------------------------------------------
#define PADE 40
#define KIND_ELEMS (128*PADE)            // 5120 ush = 10KB
#define STAGE_ELEMS (2*KIND_ELEMS)       // A, B
#define GEMM_SMEM (2*STAGE_ELEMS*2)      // 40960 B

__global__ void __launch_bounds__(256, 2) gemm_mma(
    const ush* __restrict__ Ah, const ush* __restrict__ Bh,
    float* __restrict__ C,
    ush* __restrict__ qs, ush* __restrict__ ks, ush* __restrict__ vs,
    const float* __restrict__ vres, const float* __restrict__ mix,
    int mode)
{
    extern __shared__ ush sh[];
    const int tid  = threadIdx.x;
    const int wid  = tid >> 5, lane = tid & 31;
    const int brow = blockIdx.y * 128, bcol = blockIdx.x * 128;
    const int wm   = (wid & 3) * 32;
    const int wn   = (wid >> 2) * 64;
    const int K    = 1024;

    const uint32_t sbase = smem_u32(sh);

    float acc[2][8][4];
#pragma unroll
    for (int i = 0; i < 2; i++)
#pragma unroll
        for (int j = 0; j < 8; j++)
#pragma unroll
            for (int k = 0; k < 4; k++) acc[i][j][k] = 0.f;

    const ush* srcs[2] = {Ah, Bh};
    const int rbase[2] = {brow, bcol};

    auto cp_chunk = [&](int k0, int buf) {
#pragma unroll
        for (int kind = 0; kind < 2; kind++) {
#pragma unroll
            for (int half = 0; half < 2; half++) {
                int e = tid + half * 256;
                int row = e >> 2, ce = (e & 3) * 8;
                const ush* g = srcs[kind] + (size_t)(rbase[kind] + row) * K + k0 + ce;
                uint32_t d = sbase + (uint32_t)(buf * STAGE_ELEMS + kind * KIND_ELEMS +
                                                row * PADE + ce) * 2;
                cp16(d, g);
            }
        }
        asm volatile("cp.async.commit_group;" ::: "memory");
    };

    cp_chunk(0, 0);

    for (int c = 0; c < 32; c++) {
        int buf = c & 1;
        if (c < 31) {
            cp_chunk((c + 1) * 32, buf ^ 1);
            asm volatile("cp.async.wait_group 1;" ::: "memory");
        } else {
            asm volatile("cp.async.wait_group 0;" ::: "memory");
        }
        __syncthreads();

        uint32_t abase = sbase + (uint32_t)buf * STAGE_ELEMS * 2;

#pragma unroll
        for (int ksub = 0; ksub < 2; ksub++) {
            uint32_t a[2][4];
            {
                int arow = wm + (lane & 15);
                int acol = ksub * 16 + (lane >> 4) * 8;
#pragma unroll
                for (int ms = 0; ms < 2; ms++)
                    ldsm4(a[ms], abase + (uint32_t)((arow + ms * 16) * PADE + acol) * 2);
            }
            uint32_t b[8][2];
            {
                int bn = (lane & 7) | ((lane >> 1) & 8);
                int bk = ksub * 16 + ((lane >> 3) & 1) * 8;
#pragma unroll
                for (int g = 0; g < 4; g++) {
                    uint32_t r[4];
                    ldsm4(r, abase + (uint32_t)(KIND_ELEMS +
                          (wn + g * 16 + bn) * PADE + bk) * 2);
                    b[2 * g][0]     = r[0]; b[2 * g][1]     = r[1];
                    b[2 * g + 1][0] = r[2]; b[2 * g + 1][1] = r[3];
                }
            }
#pragma unroll
            for (int ms = 0; ms < 2; ms++)
#pragma unroll
                for (int nf = 0; nf < 8; nf++)
                    mma16816h(acc[ms][nf], a[ms], b[nf]);
        }
        __syncthreads();
    }

    if (mode == 0) {
#pragma unroll
        for (int ms = 0; ms < 2; ms++) {
            int r0 = brow + wm + ms * 16 + (lane >> 2);
#pragma unroll
            for (int nf = 0; nf < 8; nf++) {
                int cc = bcol + wn + nf * 8 + 2 * (lane & 3);
                *(float2*)(C + (size_t)r0 * 1024 + cc)       = make_float2(acc[ms][nf][0], acc[ms][nf][1]);
                *(float2*)(C + (size_t)(r0 + 8) * 1024 + cc) = make_float2(acc[ms][nf][2], acc[ms][nf][3]);
            }
        }
        return;
    }

    // fused QKV epilogue: seg 0=q (rope+scale), 1=k (rope), 2=v (mix lerp)
    const int seg  = bcol >> 10;
    const int colb = (bcol & 1023) + wn + 2 * (lane & 3);
    ush* dst = (seg == 0) ? qs : (seg == 1) ? ks : vs;
    const float qscale = (seg == 0) ? 0.125f : 1.0f;
    const float L2F = 13.2877123795494f / 32.0f;   // log2(10000)/32

#pragma unroll
    for (int ms = 0; ms < 2; ms++) {
        int r0 = brow + wm + ms * 16 + (lane >> 2);
#pragma unroll
        for (int half = 0; half < 2; half++) {
            int row = r0 + half * 8;
            int s = row & (Sn - 1);
            int bb = row >> 11;
#pragma unroll
            for (int nf = 0; nf < 8; nf++) {
                float x0 = acc[ms][nf][half * 2 + 0];
                float x1 = acc[ms][nf][half * 2 + 1];
                int colc = colb + nf * 8;
                size_t o = (size_t)row * 1024 + colc;
                float y0, y1;
                if (seg < 2) {
                    int i = (colc & 63) >> 1;
                    float inv = exp2f(-(float)i * L2F);
                    float ang = (float)s * inv;
                    float sn, cs;
                    sincosf(ang, &sn, &cs);
                    y0 = (x0 * cs - x1 * sn) * qscale;
                    y1 = (x1 * cs + x0 * sn) * qscale;
                } else {
                    int hh = (colc & 1023) >> 6;
                    int d  = colc & 63;
                    float m = mix[row * Hn + hh];
                    const float* rp = vres + (((size_t)bb * Hn + hh) * Sn + s) * Dn + d;
                    float2 rr = *(const float2*)rp;
                    y0 = x0 + (rr.x - x0) * m;
                    y1 = x1 + (rr.y - x1) * m;
                }
                *(uint32_t*)(dst + o) = packh(y0, y1);
            }
        }
    }
}

// ---------------------------------------------------------------------------
// mix/gate: (8192 x 1024) @ [Wmix | Wgate] (1024 x 32), sigmoid epilogue.
// ---------------------------------------------------------------------------
__global__ void __launch_bounds__(256) mixgate(
    const float* __restrict__ tokens, const float* __restrict__ Wmix,
    const float* __restrict__ Wgate, float* __restrict__ gmix,
    float* __restrict__ ggate)
{
    __shared__ float Ts[128][65];
    __shared__ float Ws[64][32];

    const int tid  = threadIdx.x;
    const int row0 = blockIdx.x * 128;
    const int r  = tid >> 1;
    const int cg = (tid & 1) << 4;

    float acc[16];
#pragma unroll
    for (int c = 0; c < 16; c++) acc[c] = 0.f;

    for (int k0 = 0; k0 < 1024; k0 += 64) {
#pragma unroll
        for (int u = 0; u < 8; u++) {
            int fi = tid + u * 256;
            int rr = fi >> 4;
            int cc = (fi & 15) << 2;
            float4 x = *(const float4*)(tokens + (size_t)(row0 + rr) * 1024 + k0 + cc);
            Ts[rr][cc] = x.x; Ts[rr][cc + 1] = x.y; Ts[rr][cc + 2] = x.z; Ts[rr][cc + 3] = x.w;
        }
#pragma unroll
        for (int u = 0; u < 8; u++) {
            int fi = tid + u * 256;
            int rr = fi >> 5;
            int cc = fi & 31;
            Ws[rr][cc] = (cc < 16) ? Wmix[(k0 + rr) * 16 + cc]
                                   : Wgate[(k0 + rr) * 16 + (cc - 16)];
        }
        __syncthreads();
        for (int kk = 0; kk < 64; kk++) {
            float a = Ts[r][kk];
#pragma unroll
            for (int c = 0; c < 16; c++) acc[c] += a * Ws[kk][cg + c];
        }
        __syncthreads();
    }

    const int t = row0 + r;
#pragma unroll
    for (int c = 0; c < 16; c++) {
        float sg = 1.0f / (1.0f + expf(-acc[c]));
        int col = cg + c;
        if (col < 16) gmix[t * 16 + col] = sg;
        else          ggate[t * 16 + (col - 16)] = sg;
    }
}

// ---------------------------------------------------------------------------
// Sliding-window flash attention, single fp16 operands, fp32 accumulate.
// CTA = (64-query tile, head, batch); 4 warps, warp = 16 rows x 64 keys.
// ---------------------------------------------------------------------------
#define APAD 72
#define ATT_SMEM (3*64*APAD*2)

__global__ void __launch_bounds__(128) attn_mma(
    const ush* __restrict__ qs, const ush* __restrict__ kh,
    const ush* __restrict__ vh, const float* __restrict__ gate,
    ush* __restrict__ ao)
{
    extern __shared__ ush smA[];
    ush* Qs = smA;
    ush* Ks = Qs + 64 * APAD;
    ush* Vs = Ks + 64 * APAD;

    const int b = blockIdx.z, h = blockIdx.y, q0 = blockIdx.x * 64;
    const int tid = threadIdx.x, wid = tid >> 5, lane = tid & 31;
    const int wm = wid * 16;
    const size_t bbase = (size_t)b * Sn;
    const int hoff = h * Dn;

#pragma unroll
    for (int i = 0; i < 4; i++) {
        int e = tid + i * 128;
        int row = e >> 3, c = (e & 7) * 8;
        size_t g = (bbase + q0 + row) * (size_t)HDn + hoff + c;
        *(uint4*)(Qs + row * APAD + c) = *(const uint4*)(qs + g);
    }
    __syncthreads();

    uint32_t qf[4][4];
    {
        uint32_t qb = smem_u32(Qs);
        int arow = wm + (lane & 15);
        int ac0  = (lane >> 4) * 8;
#pragma unroll
        for (int ks = 0; ks < 4; ks++)
            ldsm4(qf[ks], qb + (arow * APAD + ks * 16 + ac0) * 2);
    }

    float mi0 = -1e30f, mi1 = -1e30f, li0 = 0.f, li1 = 0.f;
    float accO[8][4];
#pragma unroll
    for (int i = 0; i < 8; i++)
#pragma unroll
        for (int j = 0; j < 4; j++) accO[i][j] = 0.f;

    const int jt_lo = (q0 >= WIN) ? ((q0 - WIN) >> 6) : 0;
    const int jt_hi = q0 >> 6;
    const int gi0 = q0 + wm + (lane >> 2);
    const int gi1 = gi0 + 8;

    const uint32_t kb = smem_u32(Ks);
    const uint32_t vb = smem_u32(Vs);
    const int bn  = (lane & 7) | ((lane >> 1) & 8);
    const int bk8 = ((lane >> 3) & 1) * 8;
    const int vr0 = lane & 15;
    const int vc8 = (lane >> 4) * 8;

    for (int jt = jt_lo; jt <= jt_hi; jt++) {
        const int j0 = jt * 64;
#pragma unroll
        for (int i = 0; i < 4; i++) {
            int e = tid + i * 128;
            int row = e >> 3, c = (e & 7) * 8;
            size_t g = (bbase + j0 + row) * (size_t)HDn + hoff + c;
            *(uint4*)(Ks + row * APAD + c) = *(const uint4*)(kh + g);
            *(uint4*)(Vs + row * APAD + c) = *(const uint4*)(vh + g);
        }
        __syncthreads();

        float s[8][4];
#pragma unroll
        for (int i = 0; i < 8; i++)
#pragma unroll
            for (int j = 0; j < 4; j++) s[i][j] = 0.f;

        // S = Q K^T
#pragma unroll
        for (int ks = 0; ks < 4; ks++) {
#pragma unroll
            for (int g2 = 0; g2 < 4; g2++) {
                uint32_t off = (uint32_t)(((g2 * 16 + bn) * APAD + ks * 16 + bk8) * 2);
                uint32_t rh[4];
                ldsm4(rh, kb + off);
                uint32_t bh0[2] = {rh[0], rh[1]}, bh1[2] = {rh[2], rh[3]};
                mma16816h(s[2*g2],   qf[ks], bh0);
                mma16816h(s[2*g2+1], qf[ks], bh1);
            }
        }

        if (jt == jt_hi || (jt == jt_lo && q0 >= WIN)) {
#pragma unroll
            for (int nf = 0; nf < 8; nf++) {
                int cbase = j0 + nf * 8 + (lane & 3) * 2;
#pragma unroll
                for (int jj = 0; jj < 2; jj++) {
                    int gj = cbase + jj;
                    int d0 = gi0 - gj, d1 = gi1 - gj;
                    if (d0 < 0 || d0 > WIN) s[nf][jj]     = -1e30f;
                    if (d1 < 0 || d1 > WIN) s[nf][2 + jj] = -1e30f;
                }
            }
        }

        float mt0 = -1e30f, mt1 = -1e30f;
#pragma unroll
        for (int nf = 0; nf < 8; nf++) {
            mt0 = fmaxf(mt0, fmaxf(s[nf][0], s[nf][1]));
            mt1 = fmaxf(mt1, fmaxf(s[nf][2], s[nf][3]));
        }
        mt0 = fmaxf(mt0, __shfl_xor_sync(0xffffffffu, mt0, 1));
        mt0 = fmaxf(mt0, __shfl_xor_sync(0xffffffffu, mt0, 2));
        mt1 = fmaxf(mt1, __shfl_xor_sync(0xffffffffu, mt1, 1));
        mt1 = fmaxf(mt1, __shfl_xor_sync(0xffffffffu, mt1, 2));

        float mn0 = fmaxf(mi0, mt0), mn1 = fmaxf(mi1, mt1);
        float f0 = __expf(mi0 - mn0), f1 = __expf(mi1 - mn1);
        mi0 = mn0; mi1 = mn1;

        float su0 = 0.f, su1 = 0.f;
#pragma unroll
        for (int nf = 0; nf < 8; nf++) {
            s[nf][0] = __expf(s[nf][0] - mn0);
            s[nf][1] = __expf(s[nf][1] - mn0);
            s[nf][2] = __expf(s[nf][2] - mn1);
            s[nf][3] = __expf(s[nf][3] - mn1);
            su0 += s[nf][0] + s[nf][1];
            su1 += s[nf][2] + s[nf][3];
        }
        su0 += __shfl_xor_sync(0xffffffffu, su0, 1);
        su0 += __shfl_xor_sync(0xffffffffu, su0, 2);
        su1 += __shfl_xor_sync(0xffffffffu, su1, 1);
        su1 += __shfl_xor_sync(0xffffffffu, su1, 2);
        li0 = li0 * f0 + su0;
        li1 = li1 * f1 + su1;
#pragma unroll
        for (int nf = 0; nf < 8; nf++) {
            accO[nf][0] *= f0; accO[nf][1] *= f0;
            accO[nf][2] *= f1; accO[nf][3] *= f1;
        }

        // O += P V (P single fp16)
#pragma unroll
        for (int ks = 0; ks < 4; ks++) {
            uint32_t ph[4];
            const float* p0 = s[2 * ks];
            const float* p1 = s[2 * ks + 1];
            ph[0] = packh(p0[0], p0[1]);
            ph[1] = packh(p0[2], p0[3]);
            ph[2] = packh(p1[0], p1[1]);
            ph[3] = packh(p1[2], p1[3]);
#pragma unroll
            for (int g2 = 0; g2 < 4; g2++) {
                uint32_t off = (uint32_t)(((ks * 16 + vr0) * APAD + g2 * 16 + vc8) * 2);
                uint32_t rh[4];
                ldsm4t(rh, vb + off);
                uint32_t bh0[2] = {rh[0], rh[1]}, bh1[2] = {rh[2], rh[3]};
                mma16816h(accO[2*g2],   ph, bh0);
                mma16816h(accO[2*g2+1], ph, bh1);
            }
        }
        __syncthreads();
    }

    float g0 = gate[(bbase + gi0) * Hn + h];
    float g1 = gate[(bbase + gi1) * Hn + h];
    float sc0 = g0 / li0, sc1 = g1 / li1;
#pragma unroll
    for (int nf = 0; nf < 8; nf++) {
        int col = hoff + nf * 8 + (lane & 3) * 2;
        size_t i0 = (bbase + gi0) * (size_t)HDn + col;
        size_t i1 = (bbase + gi1) * (size_t)HDn + col;
        *(uint32_t*)(ao + i0) = packh(accO[nf][0] * sc0, accO[nf][1] * sc0);
        *(uint32_t*)(ao + i1) = packh(accO[nf][2] * sc1, accO[nf][3] * sc1);
    }
}

// ---------------------------------------------------------------------------
extern "C" void kernel_launch(void* const* d_in, const int* in_sizes, int n_in,
                              void* d_out, int out_size)
{
    const float* tokens = (const float*)d_in[0];
    const float* vres   = (const float*)d_in[1];
    const float* Wq     = (const float*)d_in[2];
    const float* Wkv    = (const float*)d_in[3];
    const float* Wout   = (const float*)d_in[4];
    const float* Wgate  = (const float*)d_in[5];
    const float* Wmix   = (const float*)d_in[6];
    float* out = (float*)d_out;

    float *pmix, *pgate;
    ush *tk, *ao, *wah, *woh, *qsp, *ksp, *vsp;
    cudaGetSymbolAddress((void**)&pmix, g_mix);
    cudaGetSymbolAddress((void**)&pgate,g_gate);
    cudaGetSymbolAddress((void**)&tk,   g_tok);
    cudaGetSymbolAddress((void**)&ao,   g_ao);
    cudaGetSymbolAddress((void**)&wah,  g_wallh);
    cudaGetSymbolAddress((void**)&woh,  g_woh);
    cudaGetSymbolAddress((void**)&qsp,  g_qs);
    cudaGetSymbolAddress((void**)&ksp,  g_ks);
    cudaGetSymbolAddress((void**)&vsp,  g_vs);

    cudaFuncSetAttribute(gemm_mma, cudaFuncAttributeMaxDynamicSharedMemorySize, GEMM_SMEM);
    cudaFuncSetAttribute(attn_mma, cudaFuncAttributeMaxDynamicSharedMemorySize, ATT_SMEM);

    // 1. casts: tokens fp16; weights fp16 transposed
    conv1<<<(Tn * DIMn / 4 + 255) / 256, 256>>>(tokens, tk, Tn * DIMn / 4);
    convW<<<dim3(1024 / 32, 1024 / 32), dim3(32, 8)>>>(Wq,  wah,               1024, 1024);
    convW<<<dim3(2048 / 32, 1024 / 32), dim3(32, 8)>>>(Wkv, wah + 1024 * 1024, 1024, 2048);
    convW<<<dim3(1024 / 32, 1024 / 32), dim3(32, 8)>>>(Wout, woh, 1024, 1024);

    // 2. mix / gate logits + sigmoid
    mixgate<<<64, 256>>>(tokens, Wmix, Wgate, pmix, pgate);

    // 3. merged QKV projection with fused rope / v-mix epilogue
    gemm_mma<<<dim3(24, 64), 256, GEMM_SMEM>>>(
        tk, wah, nullptr, qsp, ksp, vsp, vres, pmix, 1);

    // 4. windowed attention (fp16) + gate, writes fp16 ao
    attn_mma<<<dim3(Sn / 64, Hn, Bn), 128, ATT_SMEM>>>(
        qsp, ksp, vsp, pgate, ao);

    // 5. output projection into d_out
    gemm_mma<<<dim3(8, 64), 256, GEMM_SMEM>>>(
        ao, woh, out, nullptr, nullptr, nullptr, nullptr, nullptr, 0);
}